// round 7
// baseline (speedup 1.0000x reference)
#include <cuda_runtime.h>
#include <cuda_fp16.h>
#include <cstdint>

// ---------------- problem constants ----------------
#define BB 32
#define NN 207
#define TT 24
#define EE 128
#define HH 8
#define HD 16
#define DMOUT 64
#define MM 32
#define G8 8                         // batches per fused block

#define OUT_N (BB * NN * TT * DMOUT)
#define ATTN_N (BB * NN * HH * TT * TT)

// P images: per (m,n): 128 k-rows x 128 n-cols fp16, swizzled (32KB)
__device__ __align__(16) __half g_Pimg[(size_t)3 * NN * 16384];
// W image: 128 k-rows x 64 n-cols fp16, swizzled 128B rows (16KB)
__device__ __align__(16) __half g_Wimg[8192];

// ---------------- helpers ----------------
__device__ __forceinline__ uint32_t smem_u32(const void* p) {
    uint32_t a;
    asm("{ .reg .u64 t; cvta.to.shared.u64 t, %1; cvt.u32.u64 %0, t; }" : "=r"(a) : "l"(p));
    return a;
}
// swizzled byte offset: 256B rows, 16B chunks ci 0..15
__device__ __forceinline__ uint32_t sw_off(int r, int ci) {
    return (uint32_t)r * 256u + (uint32_t)((ci ^ (r & 7)) << 4);
}
// swizzled byte offset: 128B rows, 16B chunks ci 0..7
__device__ __forceinline__ uint32_t sw_off64(int r, int ci) {
    return (uint32_t)r * 128u + (uint32_t)((ci ^ (r & 7)) << 4);
}
__device__ __forceinline__ void ldsm_x4(uint32_t* r, uint32_t addr) {
    asm volatile("ldmatrix.sync.aligned.m8n8.x4.shared.b16 {%0,%1,%2,%3}, [%4];"
                 : "=r"(r[0]), "=r"(r[1]), "=r"(r[2]), "=r"(r[3]) : "r"(addr));
}
__device__ __forceinline__ void ldsm_x4_t(uint32_t* r, uint32_t addr) {
    asm volatile("ldmatrix.sync.aligned.m8n8.x4.trans.shared.b16 {%0,%1,%2,%3}, [%4];"
                 : "=r"(r[0]), "=r"(r[1]), "=r"(r[2]), "=r"(r[3]) : "r"(addr));
}
__device__ __forceinline__ void mma_f16(float* d, const uint32_t* a, const uint32_t* b) {
    asm volatile("mma.sync.aligned.m16n8k16.row.col.f32.f16.f16.f32 "
                 "{%0,%1,%2,%3}, {%4,%5,%6,%7}, {%8,%9}, {%0,%1,%2,%3};"
                 : "+f"(d[0]), "+f"(d[1]), "+f"(d[2]), "+f"(d[3])
                 : "r"(a[0]), "r"(a[1]), "r"(a[2]), "r"(a[3]), "r"(b[0]), "r"(b[1]));
}
#define CP_ASYNC16(dst, src) \
    asm volatile("cp.async.cg.shared.global [%0], [%1], 16;" :: "r"(dst), "l"(src))
#define CP_COMMIT() asm volatile("cp.async.commit_group;")
#define CP_WAIT0()  asm volatile("cp.async.wait_group 0;")

// ---------------- kernel 0: build P images (fp16, swizzled) ----------------
__global__ __launch_bounds__(256, 4) void prep_P_kernel(
    const float* __restrict__ qp1, const float* __restrict__ qp2,
    const float* __restrict__ kp1, const float* __restrict__ kp2,
    const float* __restrict__ vp1, const float* __restrict__ vp2) {
    extern __shared__ float sm0[];
    float* sp1 = sm0;              // 64 x 33 (padded)
    float* sp2 = sm0 + 2112;       // 32 x 256

    const int n = blockIdx.x, m = blockIdx.y, tid = threadIdx.x;
    const float* p1 = (m == 0) ? qp1 : ((m == 1) ? kp1 : vp1);
    const float* p2 = (m == 0) ? qp2 : ((m == 1) ? kp2 : vp2);

    for (int idx = tid; idx < 2048; idx += 256)
        sp1[(idx >> 5) * 33 + (idx & 31)] = p1[(size_t)n * 2048 + idx];
    for (int i = tid; i < 2048; i += 256)
        ((float4*)sp2)[i] = ((const float4*)p2)[i];
    __syncthreads();

    char* gbase = (char*)(g_Pimg + (size_t)(m * NN + n) * 16384);
    const float4* sp2f4 = (const float4*)sp2;
#pragma unroll
    for (int it = 0; it < 16; it++) {
        int idx = it * 256 + tid;
        int group = idx >> 5, l = idx & 31;
        int c4 = (group & 7) * 4 + (l & 3);
        int k  = (group >> 3) * 8 + (l >> 2);
        const float* a = sp1 + (k >> 1) * 33;
        int boff = (k & 1) * 32 + c4;
        float4 acc = make_float4(0.f, 0.f, 0.f, 0.f);
#pragma unroll
        for (int j = 0; j < 32; j++) {
            float aj = a[j];
            float4 bv = sp2f4[j * 64 + boff];
            acc.x += aj * bv.x; acc.y += aj * bv.y; acc.z += aj * bv.z; acc.w += aj * bv.w;
        }
        __half2 p01 = __float22half2_rn(make_float2(acc.x, acc.y));
        __half2 p23 = __float22half2_rn(make_float2(acc.z, acc.w));
        uint2 pk;
        pk.x = *(uint32_t*)&p01; pk.y = *(uint32_t*)&p23;
        uint32_t off = sw_off(k, c4 >> 1) + (uint32_t)(c4 & 1) * 8u;
        *(uint2*)(gbase + off) = pk;
    }
}

// ---------------- kernel 0b: W image (fp16, 128B-row swizzle) ----------------
__global__ void prep_W_kernel(const float* __restrict__ outW) {
    int tid = threadIdx.x;
    char* gbase = (char*)g_Wimg;
#pragma unroll
    for (int it = 0; it < 16; it++) {
        int idx = it * 256 + tid;          // 4096 fp16-pair jobs
        int k = idx >> 5, n2 = idx & 31;
        float2 v = *(const float2*)(outW + k * DMOUT + 2 * n2);
        __half2 h = __float22half2_rn(v);
        uint32_t off = sw_off64(k, n2 >> 2) + (uint32_t)(n2 & 3) * 4u;
        *(uint32_t*)(gbase + off) = *(uint32_t*)&h;
    }
}

// ---------------- fused kernel ----------------
// smem bytes:
//  [A 0..49152)     192x128 fp16 swizzled (X during proj; sO during attention)
//  [B 49152..81920) 128x128 fp16 P image during proj; W image (16KB) after
//  [QKV 81920..231680) fp16 [m][g][t] rows of 130 halves (260B)
#define OFF_Bb 49152
#define OFF_QKV 81920
#define QKV_OFF(m, g, t) (OFF_QKV + (((m) * G8 + (g)) * TT + (t)) * 260)
#define SMEMF_TOTAL 231680

__global__ __launch_bounds__(512, 1) void fused_kernel(
    const float* __restrict__ query, const float* __restrict__ key_,
    const float* __restrict__ value,
    const float* __restrict__ outb,
    float* __restrict__ out, float* __restrict__ attn_out, int write_attn) {
    extern __shared__ float smf[];
    char* smb = (char*)smf;
    const uint32_t sbase = smem_u32(smb);

    const int n = blockIdx.x;
    const int b0 = blockIdx.y * G8;
    const int tid = threadIdx.x, wid = tid >> 5, lane = tid & 31;
    const int wr = wid >> 2, wc = wid & 3;        // warp grid 4(M) x 4(N)
    const int grp = lane >> 2, tid4 = lane & 3;
    const int lq = lane & 7, qq = lane >> 3;

    // ===== three projections (M=192 = 8 batches x 24) =====
    for (int m = 0; m < 3; m++) {
        if (m) __syncthreads();
        {
            const char* bs = (const char*)(g_Pimg + (size_t)(m * NN + n) * 16384);
            uint32_t bd = sbase + OFF_Bb;
#pragma unroll
            for (int i = 0; i < 4; i++) {
                int c = i * 512 + tid;
                CP_ASYNC16(bd + c * 16, bs + c * 16);
            }
            CP_COMMIT();
        }
        {
            const float* x = (m == 0) ? query : ((m == 1) ? key_ : value);
#pragma unroll
            for (int it = 0; it < 12; it++) {
                int idx = it * 512 + tid;
                int r = idx >> 5, c4 = idx & 31;
                int g = r / TT, t = r - g * TT;
                float4 v = *(const float4*)(x + (((size_t)(b0 + g) * NN + n) * TT + t) * EE + 4 * c4);
                __half2 p01 = __float22half2_rn(make_float2(v.x, v.y));
                __half2 p23 = __float22half2_rn(make_float2(v.z, v.w));
                uint2 pk;
                pk.x = *(uint32_t*)&p01; pk.y = *(uint32_t*)&p23;
                uint32_t off = sw_off(r, c4 >> 1) + (uint32_t)(c4 & 1) * 8u;
                *(uint2*)(smb + off) = pk;
            }
        }
        CP_WAIT0();
        __syncthreads();

        float acc[3][4][4];
#pragma unroll
        for (int mr = 0; mr < 3; mr++)
#pragma unroll
            for (int nt = 0; nt < 4; nt++)
#pragma unroll
                for (int i = 0; i < 4; i++) acc[mr][nt][i] = 0.f;

#pragma unroll
        for (int kc = 0; kc < 8; kc++) {
            uint32_t a[3][4];
#pragma unroll
            for (int mr = 0; mr < 3; mr++) {
                int r = wr * 48 + mr * 16 + lq + (qq & 1) * 8;
                int ci = kc * 2 + (qq >> 1);
                ldsm_x4(a[mr], sbase + sw_off(r, ci));
            }
            uint32_t bf[4][2];
#pragma unroll
            for (int p = 0; p < 2; p++) {
                int r = kc * 16 + lq + (qq & 1) * 8;
                int ci = wc * 4 + p * 2 + (qq >> 1);
                uint32_t t4[4];
                ldsm_x4_t(t4, sbase + OFF_Bb + sw_off(r, ci));
                bf[2 * p][0] = t4[0]; bf[2 * p][1] = t4[1];
                bf[2 * p + 1][0] = t4[2]; bf[2 * p + 1][1] = t4[3];
            }
#pragma unroll
            for (int mr = 0; mr < 3; mr++)
#pragma unroll
                for (int nt = 0; nt < 4; nt++)
                    mma_f16(acc[mr][nt], a[mr], bf[nt]);
        }

        // epilogue: relu -> qkv fp16
#pragma unroll
        for (int mr = 0; mr < 3; mr++) {
#pragma unroll
            for (int half = 0; half < 2; half++) {
                int row = wr * 48 + mr * 16 + half * 8 + grp;
                int g = row / TT, t = row - g * TT;
                char* dst = smb + QKV_OFF(m, g, t);
#pragma unroll
                for (int nt = 0; nt < 4; nt++) {
                    int col = wc * 32 + nt * 8 + tid4 * 2;
                    __half2 hv = __float22half2_rn(make_float2(
                        fmaxf(acc[mr][nt][half * 2 + 0], 0.f),
                        fmaxf(acc[mr][nt][half * 2 + 1], 0.f)));
                    *(uint32_t*)(dst + col * 2) = *(uint32_t*)&hv;
                }
            }
        }
    }
    __syncthreads();      // qkv done; A + B regions free

    // W image async copy into B region (overlaps attention)
    {
        const char* ws = (const char*)g_Wimg;
        int c = tid;                                  // 1024 chunks of 16B
        CP_ASYNC16(sbase + OFF_Bb + c * 16, ws + c * 16);
        CP_ASYNC16(sbase + OFF_Bb + (512 + c) * 16, ws + (512 + c) * 16);
        CP_COMMIT();
    }

    // ===== attention: 4 reps x (2 batch-slots x 8 heads), sync-free =====
    const int slot = wid >> 3, h = wid & 7;
    const int t = lane;
#pragma unroll
    for (int rep = 0; rep < 4; rep++) {
        const int gg = rep * 2 + slot;
        const long bn = (long)(b0 + gg) * NN + n;
        if (t < TT) {
            float qr[HD];
            {
                const uint32_t* qp = (const uint32_t*)(smb + QKV_OFF(0, gg, t) + h * 32);
#pragma unroll
                for (int e2 = 0; e2 < 8; e2++) {
                    uint32_t u = qp[e2];
                    float2 f = __half22float2(*(const __half2*)&u);
                    qr[2 * e2] = f.x; qr[2 * e2 + 1] = f.y;
                }
            }
            float sc[TT];
#pragma unroll
            for (int s = 0; s < TT; s++) {
                const uint32_t* kp = (const uint32_t*)(smb + QKV_OFF(1, gg, s) + h * 32);
                float a = 0.f;
#pragma unroll
                for (int e2 = 0; e2 < 8; e2++) {
                    uint32_t u = kp[e2];
                    float2 f = __half22float2(*(const __half2*)&u);
                    a += qr[2 * e2] * f.x + qr[2 * e2 + 1] * f.y;
                }
                sc[s] = a;
            }
            const float scale = 0.25f;
            float mx = -1e30f;
#pragma unroll
            for (int s = 0; s < TT; s++) if (s <= t) mx = fmaxf(mx, sc[s] * scale);
            float sum = 0.f, pr[TT];
#pragma unroll
            for (int s = 0; s < TT; s++) {
                float p = (s <= t) ? __expf(sc[s] * scale - mx) : 0.f;
                pr[s] = p; sum += p;
            }
            float inv = 1.f / sum;
#pragma unroll
            for (int s = 0; s < TT; s++) pr[s] *= inv;

            float o[HD];
#pragma unroll
            for (int d = 0; d < HD; d++) o[d] = 0.f;
#pragma unroll
            for (int s = 0; s < TT; s++) {
                const uint32_t* vp = (const uint32_t*)(smb + QKV_OFF(2, gg, s) + h * 32);
                float pv = pr[s];
#pragma unroll
                for (int d2 = 0; d2 < 8; d2++) {
                    uint32_t u = vp[d2];
                    float2 f = __half22float2(*(const __half2*)&u);
                    o[2 * d2] += pv * f.x; o[2 * d2 + 1] += pv * f.y;
                }
            }
            // write sO as fp16 into A image: row = gg*24 + t, cols h*16..h*16+15
            {
                int row = gg * TT + t;
                uint4 pk0, pk1;
                __half2 v0 = __float22half2_rn(make_float2(o[0], o[1]));
                __half2 v1 = __float22half2_rn(make_float2(o[2], o[3]));
                __half2 v2 = __float22half2_rn(make_float2(o[4], o[5]));
                __half2 v3 = __float22half2_rn(make_float2(o[6], o[7]));
                __half2 v4 = __float22half2_rn(make_float2(o[8], o[9]));
                __half2 v5 = __float22half2_rn(make_float2(o[10], o[11]));
                __half2 v6 = __float22half2_rn(make_float2(o[12], o[13]));
                __half2 v7 = __float22half2_rn(make_float2(o[14], o[15]));
                pk0.x = *(uint32_t*)&v0; pk0.y = *(uint32_t*)&v1;
                pk0.z = *(uint32_t*)&v2; pk0.w = *(uint32_t*)&v3;
                pk1.x = *(uint32_t*)&v4; pk1.y = *(uint32_t*)&v5;
                pk1.z = *(uint32_t*)&v6; pk1.w = *(uint32_t*)&v7;
                *(uint4*)(smb + sw_off(row, h * 2))     = pk0;
                *(uint4*)(smb + sw_off(row, h * 2 + 1)) = pk1;
            }
            if (write_attn) {
                float* ab = attn_out + (((bn * HH) + h) * TT + t) * TT;
#pragma unroll
                for (int s4 = 0; s4 < TT / 4; s4++)
                    ((float4*)ab)[s4] = make_float4(pr[4 * s4], pr[4 * s4 + 1], pr[4 * s4 + 2], pr[4 * s4 + 3]);
            }
        }
    }
    CP_WAIT0();
    __syncthreads();      // sO image complete, W image ready

    // ===== output projection: (192x128) @ (128x64) mma, bias+relu =====
    {
        float acc[3][2][4];
#pragma unroll
        for (int mr = 0; mr < 3; mr++)
#pragma unroll
            for (int nt = 0; nt < 2; nt++)
#pragma unroll
                for (int i = 0; i < 4; i++) acc[mr][nt][i] = 0.f;

#pragma unroll
        for (int kc = 0; kc < 8; kc++) {
            uint32_t a[3][4];
#pragma unroll
            for (int mr = 0; mr < 3; mr++) {
                int r = wr * 48 + mr * 16 + lq + (qq & 1) * 8;
                int ci = kc * 2 + (qq >> 1);
                ldsm_x4(a[mr], sbase + sw_off(r, ci));
            }
            uint32_t bf[2][2];
            {
                int r = kc * 16 + lq + (qq & 1) * 8;
                int ci = wc * 2 + (qq >> 1);
                uint32_t t4[4];
                ldsm_x4_t(t4, sbase + OFF_Bb + sw_off64(r, ci));
                bf[0][0] = t4[0]; bf[0][1] = t4[1];
                bf[1][0] = t4[2]; bf[1][1] = t4[3];
            }
#pragma unroll
            for (int mr = 0; mr < 3; mr++)
#pragma unroll
                for (int nt = 0; nt < 2; nt++)
                    mma_f16(acc[mr][nt], a[mr], bf[nt]);
        }

        // epilogue: bias + relu -> out
        float2 bias[2];
#pragma unroll
        for (int nt = 0; nt < 2; nt++) {
            int col = wc * 16 + nt * 8 + tid4 * 2;
            bias[nt] = make_float2(__ldg(outb + col), __ldg(outb + col + 1));
        }
#pragma unroll
        for (int mr = 0; mr < 3; mr++) {
#pragma unroll
            for (int half = 0; half < 2; half++) {
                int row = wr * 48 + mr * 16 + half * 8 + grp;
                int g = row / TT, t2 = row - g * TT;
                const long bn = (long)(b0 + g) * NN + n;
                float* op = out + ((bn * TT) + t2) * DMOUT;
#pragma unroll
                for (int nt = 0; nt < 2; nt++) {
                    int col = wc * 16 + nt * 8 + tid4 * 2;
                    *(float2*)(op + col) = make_float2(
                        fmaxf(acc[mr][nt][half * 2 + 0] + bias[nt].x, 0.f),
                        fmaxf(acc[mr][nt][half * 2 + 1] + bias[nt].y, 0.f));
                }
            }
        }
    }
}

// ---------------- launch ----------------
extern "C" void kernel_launch(void* const* d_in, const int* in_sizes, int n_in,
                              void* d_out, int out_size) {
    const float* query = (const float*)d_in[0];
    const float* key_  = (const float*)d_in[1];
    const float* value = (const float*)d_in[2];
    const float* qp1 = (const float*)d_in[4];
    const float* qp2 = (const float*)d_in[5];
    const float* kp1 = (const float*)d_in[6];
    const float* kp2 = (const float*)d_in[7];
    const float* vp1 = (const float*)d_in[8];
    const float* vp2 = (const float*)d_in[9];
    const float* outW = (const float*)d_in[10];
    const float* outb = (const float*)d_in[11];

    float* out = (float*)d_out;
    int write_attn = (out_size >= OUT_N + ATTN_N) ? 1 : 0;

    static int attr_done = 0;
    if (!attr_done) {
        cudaFuncSetAttribute(prep_P_kernel, cudaFuncAttributeMaxDynamicSharedMemorySize, 41216);
        cudaFuncSetAttribute(fused_kernel, cudaFuncAttributeMaxDynamicSharedMemorySize, SMEMF_TOTAL);
        attr_done = 1;
    }

    prep_P_kernel<<<dim3(NN, 3), 256, 41216>>>(qp1, qp2, kp1, kp2, vp1, vp2);
    prep_W_kernel<<<1, 256>>>(outW);
    fused_kernel<<<dim3(NN, BB / G8), 512, SMEMF_TOTAL>>>(
        query, key_, value, outb, out, out + OUT_N, write_attn);
}

// round 8
// speedup vs baseline: 1.4519x; 1.4519x over previous
#include <cuda_runtime.h>
#include <cuda_fp16.h>
#include <cstdint>

// ---------------- problem constants ----------------
#define BB 32
#define NN 207
#define TT 24
#define EE 128
#define HH 8
#define HD 16
#define DMOUT 64
#define MM 32
#define G8 8                         // batches per fused block

#define OUT_N (BB * NN * TT * DMOUT)
#define ATTN_N (BB * NN * HH * TT * TT)

// P images: per (m,n): 128 k-rows x 128 n-cols fp16, swizzled (32KB)
__device__ __align__(16) __half g_Pimg[(size_t)3 * NN * 16384];

// ---------------- helpers ----------------
__device__ __forceinline__ uint32_t smem_u32(const void* p) {
    uint32_t a;
    asm("{ .reg .u64 t; cvta.to.shared.u64 t, %1; cvt.u32.u64 %0, t; }" : "=r"(a) : "l"(p));
    return a;
}
// swizzled byte offset: 256B rows, 16B chunks ci 0..15
__device__ __forceinline__ uint32_t sw_off(int r, int ci) {
    return (uint32_t)r * 256u + (uint32_t)((ci ^ (r & 7)) << 4);
}
__device__ __forceinline__ void ldsm_x4(uint32_t* r, uint32_t addr) {
    asm volatile("ldmatrix.sync.aligned.m8n8.x4.shared.b16 {%0,%1,%2,%3}, [%4];"
                 : "=r"(r[0]), "=r"(r[1]), "=r"(r[2]), "=r"(r[3]) : "r"(addr));
}
__device__ __forceinline__ void ldsm_x4_t(uint32_t* r, uint32_t addr) {
    asm volatile("ldmatrix.sync.aligned.m8n8.x4.trans.shared.b16 {%0,%1,%2,%3}, [%4];"
                 : "=r"(r[0]), "=r"(r[1]), "=r"(r[2]), "=r"(r[3]) : "r"(addr));
}
__device__ __forceinline__ void mma_f16(float* d, const uint32_t* a, const uint32_t* b) {
    asm volatile("mma.sync.aligned.m16n8k16.row.col.f32.f16.f16.f32 "
                 "{%0,%1,%2,%3}, {%4,%5,%6,%7}, {%8,%9}, {%0,%1,%2,%3};"
                 : "+f"(d[0]), "+f"(d[1]), "+f"(d[2]), "+f"(d[3])
                 : "r"(a[0]), "r"(a[1]), "r"(a[2]), "r"(a[3]), "r"(b[0]), "r"(b[1]));
}
#define CP_ASYNC16(dst, src) \
    asm volatile("cp.async.cg.shared.global [%0], [%1], 16;" :: "r"(dst), "l"(src))
#define CP_COMMIT() asm volatile("cp.async.commit_group;")
#define CP_WAIT0()  asm volatile("cp.async.wait_group 0;")

// ---------------- kernel 0: build P images (fp16, swizzled; smem-staged, coalesced store) ----------------
__global__ __launch_bounds__(256, 2) void prep_P_kernel(
    const float* __restrict__ qp1, const float* __restrict__ qp2,
    const float* __restrict__ kp1, const float* __restrict__ kp2,
    const float* __restrict__ vp1, const float* __restrict__ vp2) {
    extern __shared__ float sm0[];
    float* sp1 = sm0;                                  // 64 x 33 (padded)
    float* sp2 = sm0 + 2112;                           // 32 x 256
    char* img = (char*)(sm0 + 2112 + 8192);            // 32KB fp16 swizzled image

    const int n = blockIdx.x, m = blockIdx.y, tid = threadIdx.x;
    const float* p1 = (m == 0) ? qp1 : ((m == 1) ? kp1 : vp1);
    const float* p2 = (m == 0) ? qp2 : ((m == 1) ? kp2 : vp2);

    for (int idx = tid; idx < 2048; idx += 256)
        sp1[(idx >> 5) * 33 + (idx & 31)] = p1[(size_t)n * 2048 + idx];
    for (int i = tid; i < 2048; i += 256)
        ((float4*)sp2)[i] = ((const float4*)p2)[i];
    __syncthreads();

    const float4* sp2f4 = (const float4*)sp2;
#pragma unroll
    for (int it = 0; it < 16; it++) {
        int idx = it * 256 + tid;                  // 4096 float4 jobs
        int group = idx >> 5, l = idx & 31;
        int c4 = (group & 7) * 4 + (l & 3);        // 0..31
        int k  = (group >> 3) * 8 + (l >> 2);      // 0..127
        const float* a = sp1 + (k >> 1) * 33;
        int boff = (k & 1) * 32 + c4;
        float4 acc = make_float4(0.f, 0.f, 0.f, 0.f);
#pragma unroll
        for (int j = 0; j < 32; j++) {
            float aj = a[j];
            float4 bv = sp2f4[j * 64 + boff];
            acc.x += aj * bv.x; acc.y += aj * bv.y; acc.z += aj * bv.z; acc.w += aj * bv.w;
        }
        __half2 p01 = __float22half2_rn(make_float2(acc.x, acc.y));
        __half2 p23 = __float22half2_rn(make_float2(acc.z, acc.w));
        uint2 pk;
        pk.x = *(uint32_t*)&p01; pk.y = *(uint32_t*)&p23;
        uint32_t off = sw_off(k, c4 >> 1) + (uint32_t)(c4 & 1) * 8u;
        *(uint2*)(img + off) = pk;
    }
    __syncthreads();

    // coalesced bulk copy: 2048 float4 = 32KB
    float4* dst = (float4*)(g_Pimg + (size_t)(m * NN + n) * 16384);
    const float4* src = (const float4*)img;
#pragma unroll
    for (int i = 0; i < 8; i++)
        dst[i * 256 + tid] = src[i * 256 + tid];
}

// ---------------- fused kernel: 8 batches per block (R6 form) ----------------
// smem bytes:
//  [A 0..49152)   192x128 fp16 swizzled
//  [B 49152..81920) 128x128 fp16 swizzled P image
//  [QKV 81920..231680) fp16 [m][g][t] rows of 130 halves (260B)
// post-GEMM reuse of A+B region: W @0 (32KB), bias @32768, sO slots @33024 (2 x 24x132 f32)
#define OFF_Bb 49152
#define OFF_QKV 81920
#define QKV_OFF(m, g, t) (OFF_QKV + (((m) * G8 + (g)) * TT + (t)) * 260)
#define OFF_BIAS 32768
#define OFF_SO 33024
#define SO_SLOT 12672
#define SMEMF_TOTAL 231680

__global__ __launch_bounds__(512, 1) void fused_kernel(
    const float* __restrict__ query, const float* __restrict__ key_,
    const float* __restrict__ value,
    const float* __restrict__ outW, const float* __restrict__ outb,
    float* __restrict__ out, float* __restrict__ attn_out, int write_attn) {
    extern __shared__ float smf[];
    char* smb = (char*)smf;
    const uint32_t sbase = smem_u32(smb);

    const int n = blockIdx.x;
    const int b0 = blockIdx.y * G8;
    const int tid = threadIdx.x, wid = tid >> 5, lane = tid & 31;
    const int wr = wid >> 2, wc = wid & 3;        // warp grid 4(M) x 4(N)
    const int grp = lane >> 2, tid4 = lane & 3;
    const int lq = lane & 7, qq = lane >> 3;

    // ===== three projections (M=192 = 8 batches x 24) =====
    for (int m = 0; m < 3; m++) {
        if (m) __syncthreads();
        // B: async copy P image (32KB)
        {
            const char* bs = (const char*)(g_Pimg + (size_t)(m * NN + n) * 16384);
            uint32_t bd = sbase + OFF_Bb;
#pragma unroll
            for (int i = 0; i < 4; i++) {
                int c = i * 512 + tid;
                CP_ASYNC16(bd + c * 16, bs + c * 16);
            }
            CP_COMMIT();
        }
        // A: 192 rows x 128 fp32 -> fp16 swizzled
        {
            const float* x = (m == 0) ? query : ((m == 1) ? key_ : value);
#pragma unroll
            for (int it = 0; it < 12; it++) {
                int idx = it * 512 + tid;          // 6144 float4 jobs
                int r = idx >> 5, c4 = idx & 31;
                int g = r / TT, t = r - g * TT;
                float4 v = *(const float4*)(x + (((size_t)(b0 + g) * NN + n) * TT + t) * EE + 4 * c4);
                __half2 p01 = __float22half2_rn(make_float2(v.x, v.y));
                __half2 p23 = __float22half2_rn(make_float2(v.z, v.w));
                uint2 pk;
                pk.x = *(uint32_t*)&p01; pk.y = *(uint32_t*)&p23;
                uint32_t off = sw_off(r, c4 >> 1) + (uint32_t)(c4 & 1) * 8u;
                *(uint2*)(smb + off) = pk;
            }
        }
        CP_WAIT0();
        __syncthreads();

        // GEMM 192 x 128 x 128, single pass fp16
        float acc[3][4][4];
#pragma unroll
        for (int mr = 0; mr < 3; mr++)
#pragma unroll
            for (int nt = 0; nt < 4; nt++)
#pragma unroll
                for (int i = 0; i < 4; i++) acc[mr][nt][i] = 0.f;

#pragma unroll
        for (int kc = 0; kc < 8; kc++) {
            uint32_t a[3][4];
#pragma unroll
            for (int mr = 0; mr < 3; mr++) {
                int r = wr * 48 + mr * 16 + lq + (qq & 1) * 8;
                int ci = kc * 2 + (qq >> 1);
                ldsm_x4(a[mr], sbase + sw_off(r, ci));
            }
            uint32_t bf[4][2];
#pragma unroll
            for (int p = 0; p < 2; p++) {
                int r = kc * 16 + lq + (qq & 1) * 8;
                int ci = wc * 4 + p * 2 + (qq >> 1);
                uint32_t t4[4];
                ldsm_x4_t(t4, sbase + OFF_Bb + sw_off(r, ci));
                bf[2 * p][0] = t4[0]; bf[2 * p][1] = t4[1];
                bf[2 * p + 1][0] = t4[2]; bf[2 * p + 1][1] = t4[3];
            }
#pragma unroll
            for (int mr = 0; mr < 3; mr++)
#pragma unroll
                for (int nt = 0; nt < 4; nt++)
                    mma_f16(acc[mr][nt], a[mr], bf[nt]);
        }

        // epilogue: relu -> qkv fp16
#pragma unroll
        for (int mr = 0; mr < 3; mr++) {
#pragma unroll
            for (int half = 0; half < 2; half++) {
                int row = wr * 48 + mr * 16 + half * 8 + grp;
                int g = row / TT, t = row - g * TT;
                char* dst = smb + QKV_OFF(m, g, t);
#pragma unroll
                for (int nt = 0; nt < 4; nt++) {
                    int col = wc * 32 + nt * 8 + tid4 * 2;
                    __half2 hv = __float22half2_rn(make_float2(
                        fmaxf(acc[mr][nt][half * 2 + 0], 0.f),
                        fmaxf(acc[mr][nt][half * 2 + 1], 0.f)));
                    *(uint32_t*)(dst + col * 2) = *(uint32_t*)&hv;
                }
            }
        }
    }
    __syncthreads();      // qkv complete; A+B regions free

    // W + bias async copy (overlaps attention)
    {
        const char* ws = (const char*)outW;
#pragma unroll
        for (int i = 0; i < 4; i++) {
            int c = i * 512 + tid;
            CP_ASYNC16(sbase + c * 16, ws + c * 16);
        }
        if (tid < 16) CP_ASYNC16(sbase + OFF_BIAS + tid * 16, ((const char*)outb) + tid * 16);
        CP_COMMIT();
    }

    // ===== attention + output proj: 4 reps x 2 batches =====
    for (int rep = 0; rep < 4; rep++) {
        if (rep) __syncthreads();    // prev rep's proj done reading sO
        const int slot = wid >> 3, h = wid & 7;
        const int gg = rep * 2 + slot;
        const long bn = (long)(b0 + gg) * NN + n;
        const int t = lane;
        if (t < TT) {
            float qr[HD];
            {
                const uint32_t* qp = (const uint32_t*)(smb + QKV_OFF(0, gg, t) + h * 32);
#pragma unroll
                for (int e2 = 0; e2 < 8; e2++) {
                    uint32_t u = qp[e2];
                    float2 f = __half22float2(*(const __half2*)&u);
                    qr[2 * e2] = f.x; qr[2 * e2 + 1] = f.y;
                }
            }
            float sc[TT];
#pragma unroll
            for (int s = 0; s < TT; s++) {
                const uint32_t* kp = (const uint32_t*)(smb + QKV_OFF(1, gg, s) + h * 32);
                float a = 0.f;
#pragma unroll
                for (int e2 = 0; e2 < 8; e2++) {
                    uint32_t u = kp[e2];
                    float2 f = __half22float2(*(const __half2*)&u);
                    a += qr[2 * e2] * f.x + qr[2 * e2 + 1] * f.y;
                }
                sc[s] = a;
            }
            const float scale = 0.25f;
            float mx = -1e30f;
#pragma unroll
            for (int s = 0; s < TT; s++) if (s <= t) mx = fmaxf(mx, sc[s] * scale);
            float sum = 0.f, pr[TT];
#pragma unroll
            for (int s = 0; s < TT; s++) {
                float p = (s <= t) ? __expf(sc[s] * scale - mx) : 0.f;
                pr[s] = p; sum += p;
            }
            float inv = 1.f / sum;
#pragma unroll
            for (int s = 0; s < TT; s++) pr[s] *= inv;

            float o[HD];
#pragma unroll
            for (int d = 0; d < HD; d++) o[d] = 0.f;
#pragma unroll
            for (int s = 0; s < TT; s++) {
                const uint32_t* vp = (const uint32_t*)(smb + QKV_OFF(2, gg, s) + h * 32);
                float pv = pr[s];
#pragma unroll
                for (int d2 = 0; d2 < 8; d2++) {
                    uint32_t u = vp[d2];
                    float2 f = __half22float2(*(const __half2*)&u);
                    o[2 * d2] += pv * f.x; o[2 * d2 + 1] += pv * f.y;
                }
            }
            float* so = smf + (OFF_SO / 4) + slot * (SO_SLOT / 4) + t * 132 + h * HD;
#pragma unroll
            for (int d = 0; d < HD; d += 2)
                *(float2*)(so + d) = make_float2(o[d], o[d + 1]);

            if (write_attn) {
                float* ab = attn_out + (((bn * HH) + h) * TT + t) * TT;
#pragma unroll
                for (int s4 = 0; s4 < TT / 4; s4++)
                    ((float4*)ab)[s4] = make_float4(pr[4 * s4], pr[4 * s4 + 1], pr[4 * s4 + 2], pr[4 * s4 + 3]);
            }
        }
        if (rep == 0) CP_WAIT0();
        __syncthreads();   // sO ready, W ready

        // output proj: slot's 8 warps handle 24 rows (3 each)
        {
            const int slot2 = wid >> 3;
            const int w8 = wid & 7;
            const int gg2 = rep * 2 + slot2;
            const long bn2 = (long)(b0 + gg2) * NN + n;
            const float* soB = smf + (OFF_SO / 4) + slot2 * (SO_SLOT / 4);
            float facc[3][2];
#pragma unroll
            for (int r = 0; r < 3; r++) { facc[r][0] = 0.f; facc[r][1] = 0.f; }
#pragma unroll 4
            for (int i = 0; i < EE; i++) {
                float2 wv = *(const float2*)(smf + i * DMOUT + 2 * lane);
                float a0 = soB[(w8 * 3 + 0) * 132 + i];
                float a1 = soB[(w8 * 3 + 1) * 132 + i];
                float a2 = soB[(w8 * 3 + 2) * 132 + i];
                facc[0][0] += a0 * wv.x; facc[0][1] += a0 * wv.y;
                facc[1][0] += a1 * wv.x; facc[1][1] += a1 * wv.y;
                facc[2][0] += a2 * wv.x; facc[2][1] += a2 * wv.y;
            }
            float bb0 = smf[OFF_BIAS / 4 + 2 * lane], bb1 = smf[OFF_BIAS / 4 + 2 * lane + 1];
#pragma unroll
            for (int r = 0; r < 3; r++) {
                int trow = w8 * 3 + r;
                float* op = out + ((bn2 * TT) + trow) * DMOUT + 2 * lane;
                *(float2*)op = make_float2(fmaxf(facc[r][0] + bb0, 0.f), fmaxf(facc[r][1] + bb1, 0.f));
            }
        }
    }
}

// ---------------- launch ----------------
extern "C" void kernel_launch(void* const* d_in, const int* in_sizes, int n_in,
                              void* d_out, int out_size) {
    const float* query = (const float*)d_in[0];
    const float* key_  = (const float*)d_in[1];
    const float* value = (const float*)d_in[2];
    const float* qp1 = (const float*)d_in[4];
    const float* qp2 = (const float*)d_in[5];
    const float* kp1 = (const float*)d_in[6];
    const float* kp2 = (const float*)d_in[7];
    const float* vp1 = (const float*)d_in[8];
    const float* vp2 = (const float*)d_in[9];
    const float* outW = (const float*)d_in[10];
    const float* outb = (const float*)d_in[11];

    float* out = (float*)d_out;
    int write_attn = (out_size >= OUT_N + ATTN_N) ? 1 : 0;

    static int attr_done = 0;
    if (!attr_done) {
        cudaFuncSetAttribute(prep_P_kernel, cudaFuncAttributeMaxDynamicSharedMemorySize, 73984);
        cudaFuncSetAttribute(fused_kernel, cudaFuncAttributeMaxDynamicSharedMemorySize, SMEMF_TOTAL);
        attr_done = 1;
    }

    prep_P_kernel<<<dim3(NN, 3), 256, 73984>>>(qp1, qp2, kp1, kp2, vp1, vp2);
    fused_kernel<<<dim3(NN, BB / G8), 512, SMEMF_TOTAL>>>(
        query, key_, value, outW, outb, out, out + OUT_N, write_attn);
}

// round 9
// speedup vs baseline: 1.8217x; 1.2547x over previous
#include <cuda_runtime.h>
#include <cuda_fp16.h>
#include <cstdint>

// ---------------- problem constants ----------------
#define BB 32
#define NN 207
#define TT 24
#define EE 128
#define HH 8
#define HD 16
#define DMOUT 64
#define MM 32
#define G8 8                         // batches per fused block

#define OUT_N (BB * NN * TT * DMOUT)
#define ATTN_N (BB * NN * HH * TT * TT)

// P images: per (m,n): 128 k-rows x 128 n-cols fp16, swizzled (32KB)
__device__ __align__(16) __half g_Pimg[(size_t)3 * NN * 16384];
// W image: 128 k-rows x 64 n-cols fp16, 128B-row swizzle (16KB)
__device__ __align__(16) __half g_Wimg[8192];

// ---------------- helpers ----------------
__device__ __forceinline__ uint32_t smem_u32(const void* p) {
    uint32_t a;
    asm("{ .reg .u64 t; cvta.to.shared.u64 t, %1; cvt.u32.u64 %0, t; }" : "=r"(a) : "l"(p));
    return a;
}
// swizzled byte offset: 256B rows, 16B chunks ci 0..15
__device__ __forceinline__ uint32_t sw_off(int r, int ci) {
    return (uint32_t)r * 256u + (uint32_t)((ci ^ (r & 7)) << 4);
}
// swizzled byte offset: 128B rows, 16B chunks ci 0..7
__device__ __forceinline__ uint32_t sw_off64(int r, int ci) {
    return (uint32_t)r * 128u + (uint32_t)((ci ^ (r & 7)) << 4);
}
__device__ __forceinline__ void ldsm_x4(uint32_t* r, uint32_t addr) {
    asm volatile("ldmatrix.sync.aligned.m8n8.x4.shared.b16 {%0,%1,%2,%3}, [%4];"
                 : "=r"(r[0]), "=r"(r[1]), "=r"(r[2]), "=r"(r[3]) : "r"(addr));
}
__device__ __forceinline__ void ldsm_x4_t(uint32_t* r, uint32_t addr) {
    asm volatile("ldmatrix.sync.aligned.m8n8.x4.trans.shared.b16 {%0,%1,%2,%3}, [%4];"
                 : "=r"(r[0]), "=r"(r[1]), "=r"(r[2]), "=r"(r[3]) : "r"(addr));
}
__device__ __forceinline__ void mma_f16(float* d, const uint32_t* a, const uint32_t* b) {
    asm volatile("mma.sync.aligned.m16n8k16.row.col.f32.f16.f16.f32 "
                 "{%0,%1,%2,%3}, {%4,%5,%6,%7}, {%8,%9}, {%0,%1,%2,%3};"
                 : "+f"(d[0]), "+f"(d[1]), "+f"(d[2]), "+f"(d[3])
                 : "r"(a[0]), "r"(a[1]), "r"(a[2]), "r"(a[3]), "r"(b[0]), "r"(b[1]));
}
#define CP_ASYNC16(dst, src) \
    asm volatile("cp.async.cg.shared.global [%0], [%1], 16;" :: "r"(dst), "l"(src))
#define CP_COMMIT() asm volatile("cp.async.commit_group;")
#define CP_WAIT0()  asm volatile("cp.async.wait_group 0;")

// ---------------- kernel 0: P images (fp16, swizzled; smem-staged, coalesced store) ----------------
__global__ __launch_bounds__(256, 2) void prep_P_kernel(
    const float* __restrict__ qp1, const float* __restrict__ qp2,
    const float* __restrict__ kp1, const float* __restrict__ kp2,
    const float* __restrict__ vp1, const float* __restrict__ vp2) {
    extern __shared__ float sm0[];
    float* sp1 = sm0;                                  // 64 x 33 (padded)
    float* sp2 = sm0 + 2112;                           // 32 x 256
    char* img = (char*)(sm0 + 2112 + 8192);            // 32KB fp16 swizzled image

    const int n = blockIdx.x, m = blockIdx.y, tid = threadIdx.x;
    const float* p1 = (m == 0) ? qp1 : ((m == 1) ? kp1 : vp1);
    const float* p2 = (m == 0) ? qp2 : ((m == 1) ? kp2 : vp2);

    for (int idx = tid; idx < 2048; idx += 256)
        sp1[(idx >> 5) * 33 + (idx & 31)] = p1[(size_t)n * 2048 + idx];
    for (int i = tid; i < 2048; i += 256)
        ((float4*)sp2)[i] = ((const float4*)p2)[i];
    __syncthreads();

    const float4* sp2f4 = (const float4*)sp2;
#pragma unroll
    for (int it = 0; it < 16; it++) {
        int idx = it * 256 + tid;
        int group = idx >> 5, l = idx & 31;
        int c4 = (group & 7) * 4 + (l & 3);
        int k  = (group >> 3) * 8 + (l >> 2);
        const float* a = sp1 + (k >> 1) * 33;
        int boff = (k & 1) * 32 + c4;
        float4 acc = make_float4(0.f, 0.f, 0.f, 0.f);
#pragma unroll
        for (int j = 0; j < 32; j++) {
            float aj = a[j];
            float4 bv = sp2f4[j * 64 + boff];
            acc.x += aj * bv.x; acc.y += aj * bv.y; acc.z += aj * bv.z; acc.w += aj * bv.w;
        }
        __half2 p01 = __float22half2_rn(make_float2(acc.x, acc.y));
        __half2 p23 = __float22half2_rn(make_float2(acc.z, acc.w));
        uint2 pk;
        pk.x = *(uint32_t*)&p01; pk.y = *(uint32_t*)&p23;
        uint32_t off = sw_off(k, c4 >> 1) + (uint32_t)(c4 & 1) * 8u;
        *(uint2*)(img + off) = pk;
    }
    __syncthreads();

    float4* dst = (float4*)(g_Pimg + (size_t)(m * NN + n) * 16384);
    const float4* src = (const float4*)img;
#pragma unroll
    for (int i = 0; i < 8; i++)
        dst[i * 256 + tid] = src[i * 256 + tid];
}

// ---------------- kernel 0b: W image (fp16, 128B-row swizzle) ----------------
__global__ void prep_W_kernel(const float* __restrict__ outW) {
    int tid = threadIdx.x;
    char* gbase = (char*)g_Wimg;
#pragma unroll
    for (int it = 0; it < 16; it++) {
        int idx = it * 256 + tid;          // 4096 fp16-pair jobs
        int k = idx >> 5, n2 = idx & 31;
        float2 v = *(const float2*)(outW + k * DMOUT + 2 * n2);
        __half2 h = __float22half2_rn(v);
        uint32_t off = sw_off64(k, n2 >> 2) + (uint32_t)(n2 & 3) * 4u;
        *(uint32_t*)(gbase + off) = *(uint32_t*)&h;
    }
}

// ---------------- fused kernel ----------------
// smem bytes:
//  [A 0..49152)     192x128 fp16 swizzled (X during proj; sO fp16 during attention)
//  [B 49152..81920) P image during proj; W image (16KB) during attention
//  [QKV 81920..231680) fp16 [m][g][t] rows of 130 halves (260B)
#define OFF_Bb 49152
#define OFF_QKV 81920
#define QKV_OFF(m, g, t) (OFF_QKV + (((m) * G8 + (g)) * TT + (t)) * 260)
#define SMEMF_TOTAL 231680

__global__ __launch_bounds__(512, 1) void fused_kernel(
    const float* __restrict__ query, const float* __restrict__ key_,
    const float* __restrict__ value,
    const float* __restrict__ outb,
    float* __restrict__ out, float* __restrict__ attn_out, int write_attn) {
    extern __shared__ float smf[];
    char* smb = (char*)smf;
    const uint32_t sbase = smem_u32(smb);

    const int n = blockIdx.x;
    const int b0 = blockIdx.y * G8;
    const int tid = threadIdx.x, wid = tid >> 5, lane = tid & 31;
    const int wr = wid >> 2, wc = wid & 3;        // warp grid 4(M) x 4(N)
    const int grp = lane >> 2, tid4 = lane & 3;
    const int lq = lane & 7, qq = lane >> 3;

    // ===== three projections (M=192 = 8 batches x 24) =====
    for (int m = 0; m < 3; m++) {
        if (m) __syncthreads();
        {
            const char* bs = (const char*)(g_Pimg + (size_t)(m * NN + n) * 16384);
            uint32_t bd = sbase + OFF_Bb;
#pragma unroll
            for (int i = 0; i < 4; i++) {
                int c = i * 512 + tid;
                CP_ASYNC16(bd + c * 16, bs + c * 16);
            }
            CP_COMMIT();
        }
        {
            const float* x = (m == 0) ? query : ((m == 1) ? key_ : value);
#pragma unroll
            for (int it = 0; it < 12; it++) {
                int idx = it * 512 + tid;
                int r = idx >> 5, c4 = idx & 31;
                int g = r / TT, t = r - g * TT;
                float4 v = *(const float4*)(x + (((size_t)(b0 + g) * NN + n) * TT + t) * EE + 4 * c4);
                __half2 p01 = __float22half2_rn(make_float2(v.x, v.y));
                __half2 p23 = __float22half2_rn(make_float2(v.z, v.w));
                uint2 pk;
                pk.x = *(uint32_t*)&p01; pk.y = *(uint32_t*)&p23;
                uint32_t off = sw_off(r, c4 >> 1) + (uint32_t)(c4 & 1) * 8u;
                *(uint2*)(smb + off) = pk;
            }
        }
        CP_WAIT0();
        __syncthreads();

        float acc[3][4][4];
#pragma unroll
        for (int mr = 0; mr < 3; mr++)
#pragma unroll
            for (int nt = 0; nt < 4; nt++)
#pragma unroll
                for (int i = 0; i < 4; i++) acc[mr][nt][i] = 0.f;

#pragma unroll
        for (int kc = 0; kc < 8; kc++) {
            uint32_t a[3][4];
#pragma unroll
            for (int mr = 0; mr < 3; mr++) {
                int r = wr * 48 + mr * 16 + lq + (qq & 1) * 8;
                int ci = kc * 2 + (qq >> 1);
                ldsm_x4(a[mr], sbase + sw_off(r, ci));
            }
            uint32_t bf[4][2];
#pragma unroll
            for (int p = 0; p < 2; p++) {
                int r = kc * 16 + lq + (qq & 1) * 8;
                int ci = wc * 4 + p * 2 + (qq >> 1);
                uint32_t t4[4];
                ldsm_x4_t(t4, sbase + OFF_Bb + sw_off(r, ci));
                bf[2 * p][0] = t4[0]; bf[2 * p][1] = t4[1];
                bf[2 * p + 1][0] = t4[2]; bf[2 * p + 1][1] = t4[3];
            }
#pragma unroll
            for (int mr = 0; mr < 3; mr++)
#pragma unroll
                for (int nt = 0; nt < 4; nt++)
                    mma_f16(acc[mr][nt], a[mr], bf[nt]);
        }

        // epilogue: relu -> qkv fp16
#pragma unroll
        for (int mr = 0; mr < 3; mr++) {
#pragma unroll
            for (int half = 0; half < 2; half++) {
                int row = wr * 48 + mr * 16 + half * 8 + grp;
                int g = row / TT, t = row - g * TT;
                char* dst = smb + QKV_OFF(m, g, t);
#pragma unroll
                for (int nt = 0; nt < 4; nt++) {
                    int col = wc * 32 + nt * 8 + tid4 * 2;
                    __half2 hv = __float22half2_rn(make_float2(
                        fmaxf(acc[mr][nt][half * 2 + 0], 0.f),
                        fmaxf(acc[mr][nt][half * 2 + 1], 0.f)));
                    *(uint32_t*)(dst + col * 2) = *(uint32_t*)&hv;
                }
            }
        }
    }
    __syncthreads();      // qkv done; A + B regions free

    // W image async copy into B region (overlaps attention)
    {
        const char* ws = (const char*)g_Wimg;
        CP_ASYNC16(sbase + OFF_Bb + tid * 16, ws + tid * 16);
        CP_ASYNC16(sbase + OFF_Bb + (512 + tid) * 16, ws + (512 + tid) * 16);
        CP_COMMIT();
    }

    // ===== attention: 4 reps x (2 batch-slots x 8 heads), sync-free, rolled =====
    const int slot = wid >> 3, h = wid & 7;
    const int t = lane;
#pragma unroll 1
    for (int rep = 0; rep < 4; rep++) {
        const int gg = rep * 2 + slot;
        const long bn = (long)(b0 + gg) * NN + n;
        if (t < TT) {
            float qr[HD];
            {
                const uint32_t* qp = (const uint32_t*)(smb + QKV_OFF(0, gg, t) + h * 32);
#pragma unroll
                for (int e2 = 0; e2 < 8; e2++) {
                    uint32_t u = qp[e2];
                    float2 f = __half22float2(*(const __half2*)&u);
                    qr[2 * e2] = f.x; qr[2 * e2 + 1] = f.y;
                }
            }
            float sc[TT];
#pragma unroll
            for (int s = 0; s < TT; s++) {
                const uint32_t* kp = (const uint32_t*)(smb + QKV_OFF(1, gg, s) + h * 32);
                float a = 0.f;
#pragma unroll
                for (int e2 = 0; e2 < 8; e2++) {
                    uint32_t u = kp[e2];
                    float2 f = __half22float2(*(const __half2*)&u);
                    a += qr[2 * e2] * f.x + qr[2 * e2 + 1] * f.y;
                }
                sc[s] = a;
            }
            const float scale = 0.25f;
            float mx = -1e30f;
#pragma unroll
            for (int s = 0; s < TT; s++) if (s <= t) mx = fmaxf(mx, sc[s] * scale);
            float sum = 0.f, pr[TT];
#pragma unroll
            for (int s = 0; s < TT; s++) {
                float p = (s <= t) ? __expf(sc[s] * scale - mx) : 0.f;
                pr[s] = p; sum += p;
            }
            float inv = 1.f / sum;
#pragma unroll
            for (int s = 0; s < TT; s++) pr[s] *= inv;

            float o[HD];
#pragma unroll
            for (int d = 0; d < HD; d++) o[d] = 0.f;
#pragma unroll
            for (int s = 0; s < TT; s++) {
                const uint32_t* vp = (const uint32_t*)(smb + QKV_OFF(2, gg, s) + h * 32);
                float pv = pr[s];
#pragma unroll
                for (int d2 = 0; d2 < 8; d2++) {
                    uint32_t u = vp[d2];
                    float2 f = __half22float2(*(const __half2*)&u);
                    o[2 * d2] += pv * f.x; o[2 * d2 + 1] += pv * f.y;
                }
            }
            // sO as fp16 into A image: row = gg*24 + t, cols h*16..h*16+15
            {
                int row = gg * TT + t;
                uint4 pk0, pk1;
                __half2 v0 = __float22half2_rn(make_float2(o[0], o[1]));
                __half2 v1 = __float22half2_rn(make_float2(o[2], o[3]));
                __half2 v2 = __float22half2_rn(make_float2(o[4], o[5]));
                __half2 v3 = __float22half2_rn(make_float2(o[6], o[7]));
                __half2 v4 = __float22half2_rn(make_float2(o[8], o[9]));
                __half2 v5 = __float22half2_rn(make_float2(o[10], o[11]));
                __half2 v6 = __float22half2_rn(make_float2(o[12], o[13]));
                __half2 v7 = __float22half2_rn(make_float2(o[14], o[15]));
                pk0.x = *(uint32_t*)&v0; pk0.y = *(uint32_t*)&v1;
                pk0.z = *(uint32_t*)&v2; pk0.w = *(uint32_t*)&v3;
                pk1.x = *(uint32_t*)&v4; pk1.y = *(uint32_t*)&v5;
                pk1.z = *(uint32_t*)&v6; pk1.w = *(uint32_t*)&v7;
                *(uint4*)(smb + sw_off(row, h * 2))     = pk0;
                *(uint4*)(smb + sw_off(row, h * 2 + 1)) = pk1;
            }
            if (write_attn) {
                float* ab = attn_out + (((bn * HH) + h) * TT + t) * TT;
#pragma unroll
                for (int s4 = 0; s4 < TT / 4; s4++)
                    ((float4*)ab)[s4] = make_float4(pr[4 * s4], pr[4 * s4 + 1], pr[4 * s4 + 2], pr[4 * s4 + 3]);
            }
        }
    }
    CP_WAIT0();
    __syncthreads();      // sO image complete, W image ready

    // ===== output projection: (192x128) @ (128x64) mma, bias+relu =====
    {
        float acc[3][2][4];
#pragma unroll
        for (int mr = 0; mr < 3; mr++)
#pragma unroll
            for (int nt = 0; nt < 2; nt++)
#pragma unroll
                for (int i = 0; i < 4; i++) acc[mr][nt][i] = 0.f;

#pragma unroll
        for (int kc = 0; kc < 8; kc++) {
            uint32_t a[3][4];
#pragma unroll
            for (int mr = 0; mr < 3; mr++) {
                int r = wr * 48 + mr * 16 + lq + (qq & 1) * 8;
                int ci = kc * 2 + (qq >> 1);
                ldsm_x4(a[mr], sbase + sw_off(r, ci));
            }
            uint32_t bf[2][2];
            {
                int r = kc * 16 + lq + (qq & 1) * 8;
                int ci = wc * 2 + (qq >> 1);
                uint32_t t4[4];
                ldsm_x4_t(t4, sbase + OFF_Bb + sw_off64(r, ci));
                bf[0][0] = t4[0]; bf[0][1] = t4[1];
                bf[1][0] = t4[2]; bf[1][1] = t4[3];
            }
#pragma unroll
            for (int mr = 0; mr < 3; mr++)
#pragma unroll
                for (int nt = 0; nt < 2; nt++)
                    mma_f16(acc[mr][nt], a[mr], bf[nt]);
        }

        float2 bias[2];
#pragma unroll
        for (int nt = 0; nt < 2; nt++) {
            int col = wc * 16 + nt * 8 + tid4 * 2;
            bias[nt] = make_float2(__ldg(outb + col), __ldg(outb + col + 1));
        }
#pragma unroll
        for (int mr = 0; mr < 3; mr++) {
#pragma unroll
            for (int half = 0; half < 2; half++) {
                int row = wr * 48 + mr * 16 + half * 8 + grp;
                int g = row / TT, t2 = row - g * TT;
                const long bn = (long)(b0 + g) * NN + n;
                float* op = out + ((bn * TT) + t2) * DMOUT;
#pragma unroll
                for (int nt = 0; nt < 2; nt++) {
                    int col = wc * 16 + nt * 8 + tid4 * 2;
                    *(float2*)(op + col) = make_float2(
                        fmaxf(acc[mr][nt][half * 2 + 0] + bias[nt].x, 0.f),
                        fmaxf(acc[mr][nt][half * 2 + 1] + bias[nt].y, 0.f));
                }
            }
        }
    }
}

// ---------------- launch ----------------
extern "C" void kernel_launch(void* const* d_in, const int* in_sizes, int n_in,
                              void* d_out, int out_size) {
    const float* query = (const float*)d_in[0];
    const float* key_  = (const float*)d_in[1];
    const float* value = (const float*)d_in[2];
    const float* qp1 = (const float*)d_in[4];
    const float* qp2 = (const float*)d_in[5];
    const float* kp1 = (const float*)d_in[6];
    const float* kp2 = (const float*)d_in[7];
    const float* vp1 = (const float*)d_in[8];
    const float* vp2 = (const float*)d_in[9];
    const float* outW = (const float*)d_in[10];
    const float* outb = (const float*)d_in[11];

    float* out = (float*)d_out;
    int write_attn = (out_size >= OUT_N + ATTN_N) ? 1 : 0;

    static int attr_done = 0;
    if (!attr_done) {
        cudaFuncSetAttribute(prep_P_kernel, cudaFuncAttributeMaxDynamicSharedMemorySize, 73984);
        cudaFuncSetAttribute(fused_kernel, cudaFuncAttributeMaxDynamicSharedMemorySize, SMEMF_TOTAL);
        attr_done = 1;
    }

    prep_P_kernel<<<dim3(NN, 3), 256, 73984>>>(qp1, qp2, kp1, kp2, vp1, vp2);
    prep_W_kernel<<<1, 256>>>(outW);
    fused_kernel<<<dim3(NN, BB / G8), 512, SMEMF_TOTAL>>>(
        query, key_, value, outb, out, out + OUT_N, write_attn);
}

// round 10
// speedup vs baseline: 2.1104x; 1.1585x over previous
#include <cuda_runtime.h>
#include <cuda_fp16.h>
#include <cuda_bf16.h>
#include <cstdint>

// ---------------- problem constants ----------------
#define BB 32
#define NN 207
#define TT 24
#define EE 128
#define HH 8
#define HD 16
#define DMOUT 64
#define MM 32
#define G8 8                         // batches per fused block

#define OUT_N (BB * NN * TT * DMOUT)
#define ATTN_N (BB * NN * HH * TT * TT)

// P images: per (m,n): 128 k-rows x 128 n-cols fp16, swizzled (32KB)
__device__ __align__(16) __half g_Pimg[(size_t)3 * NN * 16384];
// W image: 128 k-rows x 64 n-cols fp16, 128B-row swizzle (16KB)
__device__ __align__(16) __half g_Wimg[8192];

// ---------------- helpers ----------------
__device__ __forceinline__ uint32_t smem_u32(const void* p) {
    uint32_t a;
    asm("{ .reg .u64 t; cvta.to.shared.u64 t, %1; cvt.u32.u64 %0, t; }" : "=r"(a) : "l"(p));
    return a;
}
// swizzled byte offset: 256B rows, 16B chunks ci 0..15
__device__ __forceinline__ uint32_t sw_off(int r, int ci) {
    return (uint32_t)r * 256u + (uint32_t)((ci ^ (r & 7)) << 4);
}
// swizzled byte offset: 128B rows, 16B chunks ci 0..7
__device__ __forceinline__ uint32_t sw_off64(int r, int ci) {
    return (uint32_t)r * 128u + (uint32_t)((ci ^ (r & 7)) << 4);
}
__device__ __forceinline__ void ldsm_x4(uint32_t* r, uint32_t addr) {
    asm volatile("ldmatrix.sync.aligned.m8n8.x4.shared.b16 {%0,%1,%2,%3}, [%4];"
                 : "=r"(r[0]), "=r"(r[1]), "=r"(r[2]), "=r"(r[3]) : "r"(addr));
}
__device__ __forceinline__ void ldsm_x4_t(uint32_t* r, uint32_t addr) {
    asm volatile("ldmatrix.sync.aligned.m8n8.x4.trans.shared.b16 {%0,%1,%2,%3}, [%4];"
                 : "=r"(r[0]), "=r"(r[1]), "=r"(r[2]), "=r"(r[3]) : "r"(addr));
}
__device__ __forceinline__ void mma_f16(float* d, const uint32_t* a, const uint32_t* b) {
    asm volatile("mma.sync.aligned.m16n8k16.row.col.f32.f16.f16.f32 "
                 "{%0,%1,%2,%3}, {%4,%5,%6,%7}, {%8,%9}, {%0,%1,%2,%3};"
                 : "+f"(d[0]), "+f"(d[1]), "+f"(d[2]), "+f"(d[3])
                 : "r"(a[0]), "r"(a[1]), "r"(a[2]), "r"(a[3]), "r"(b[0]), "r"(b[1]));
}
__device__ __forceinline__ void mma_bf16(float* d, const uint32_t* a, const uint32_t* b) {
    asm volatile("mma.sync.aligned.m16n8k16.row.col.f32.bf16.bf16.f32 "
                 "{%0,%1,%2,%3}, {%4,%5,%6,%7}, {%8,%9}, {%0,%1,%2,%3};"
                 : "+f"(d[0]), "+f"(d[1]), "+f"(d[2]), "+f"(d[3])
                 : "r"(a[0]), "r"(a[1]), "r"(a[2]), "r"(a[3]), "r"(b[0]), "r"(b[1]));
}
#define CP_ASYNC16(dst, src) \
    asm volatile("cp.async.cg.shared.global [%0], [%1], 16;" :: "r"(dst), "l"(src))
#define CP_COMMIT() asm volatile("cp.async.commit_group;")
#define CP_WAIT0()  asm volatile("cp.async.wait_group 0;")

__device__ __forceinline__ uint32_t pack_bf16(float x, float y) {
    __nv_bfloat16 h0 = __float2bfloat16(x);
    __nv_bfloat16 h1 = __float2bfloat16(y);
    return (uint32_t)__bfloat16_as_ushort(h0) | ((uint32_t)__bfloat16_as_ushort(h1) << 16);
}

// ---------------- kernel 0: P images via tensor cores (bf16 3-pass split) ----------------
// P[2i+j][c] = (p1 @ p2[:, j*128:(j+1)*128])[i][c] -> two 64x128x32 GEMMs per (n,m)
// smem bytes: [Ah 0..16K)[Al 16K..32K)[B0h 32K..40K)[B0l 40K..48K)[B1h 48K..56K)[B1l 56K..64K)[img 64K..96K)
#define PP_AL   16384
#define PP_B    32768
#define PP_IMG  65536
#define PP_SMEM 98304

__global__ __launch_bounds__(256, 2) void prep_P_kernel(
    const float* __restrict__ qp1, const float* __restrict__ qp2,
    const float* __restrict__ kp1, const float* __restrict__ kp2,
    const float* __restrict__ vp1, const float* __restrict__ vp2) {
    extern __shared__ float sm0[];
    char* smb = (char*)sm0;
    const uint32_t sbase = smem_u32(smb);

    const int n = blockIdx.x, m = blockIdx.y, tid = threadIdx.x;
    const int wid = tid >> 5, lane = tid & 31;
    const int wr = wid >> 2, wc = wid & 3;       // warp grid 2(M) x 4(N)
    const int grp = lane >> 2, tid4 = lane & 3;
    const int lq = lane & 7, qq = lane >> 3;

    const float* p1 = (m == 0) ? qp1 : ((m == 1) ? kp1 : vp1);
    const float* p2 = (m == 0) ? qp2 : ((m == 1) ? kp2 : vp2);

    // stage p1 (64x32 fp32) -> Ah/Al bf16 swizzled (256B rows, chunks 0..3 used)
    {
        const float* p1b = p1 + (size_t)n * 2048;
#pragma unroll
        for (int it = 0; it < 4; it++) {
            int idx2 = it * 256 + tid;           // 1024 float2 jobs
            int r = idx2 >> 4, cp = idx2 & 15;   // row, half2-col (cols 2cp,2cp+1)
            float2 v = *(const float2*)(p1b + r * 32 + 2 * cp);
            float hx = __bfloat162float(__float2bfloat16(v.x));
            float hy = __bfloat162float(__float2bfloat16(v.y));
            uint32_t off = sw_off(r, cp >> 2) + (uint32_t)(cp & 3) * 4u;
            *(uint32_t*)(smb + off)         = pack_bf16(v.x, v.y);
            *(uint32_t*)(smb + PP_AL + off) = pack_bf16(v.x - hx, v.y - hy);
        }
    }
    // stage p2 (32x256 fp32) -> B0h/B0l/B1h/B1l bf16 swizzled (256B rows)
    {
#pragma unroll
        for (int it = 0; it < 16; it++) {
            int idx2 = it * 256 + tid;           // 4096 float2 jobs
            int r = idx2 >> 7, cp = idx2 & 127;  // cols 2cp,2cp+1 (same half-image)
            float2 v = *(const float2*)(p2 + r * 256 + 2 * cp);
            int jj = cp >> 6, lcp = cp & 63;
            float hx = __bfloat162float(__float2bfloat16(v.x));
            float hy = __bfloat162float(__float2bfloat16(v.y));
            uint32_t off = sw_off(r, lcp >> 2) + (uint32_t)(lcp & 3) * 4u;
            char* bb = smb + PP_B + jj * 16384;
            *(uint32_t*)(bb + off)        = pack_bf16(v.x, v.y);
            *(uint32_t*)(bb + 8192 + off) = pack_bf16(v.x - hx, v.y - hy);
        }
    }
    __syncthreads();

    // two GEMMs (j = 0,1): 64x128x32, bf16 3-pass split
#pragma unroll
    for (int j = 0; j < 2; j++) {
        float acc[2][4][4];
#pragma unroll
        for (int mr = 0; mr < 2; mr++)
#pragma unroll
            for (int nt = 0; nt < 4; nt++)
#pragma unroll
                for (int i = 0; i < 4; i++) acc[mr][nt][i] = 0.f;

        const uint32_t Ao[3] = {0u, PP_AL, 0u};
        const uint32_t Bo[3] = {0u, 0u, 8192u};
#pragma unroll
        for (int pass = 0; pass < 3; pass++) {
            const uint32_t aB = sbase + Ao[pass];
            const uint32_t bB = sbase + PP_B + (uint32_t)j * 16384u + Bo[pass];
#pragma unroll
            for (int kc = 0; kc < 2; kc++) {
                uint32_t a[2][4];
#pragma unroll
                for (int mr = 0; mr < 2; mr++) {
                    int r = wr * 32 + mr * 16 + lq + (qq & 1) * 8;
                    int ci = kc * 2 + (qq >> 1);
                    ldsm_x4(a[mr], aB + sw_off(r, ci));
                }
                uint32_t bf[4][2];
#pragma unroll
                for (int p = 0; p < 2; p++) {
                    int r = kc * 16 + lq + (qq & 1) * 8;
                    int ci = wc * 4 + p * 2 + (qq >> 1);
                    uint32_t t4[4];
                    ldsm_x4_t(t4, bB + sw_off(r, ci));
                    bf[2 * p][0] = t4[0]; bf[2 * p][1] = t4[1];
                    bf[2 * p + 1][0] = t4[2]; bf[2 * p + 1][1] = t4[3];
                }
#pragma unroll
                for (int mr = 0; mr < 2; mr++)
#pragma unroll
                    for (int nt = 0; nt < 4; nt++)
                        mma_bf16(acc[mr][nt], a[mr], bf[nt]);
            }
        }
        // epilogue: fp32 -> fp16 into P image, row k = 2*i + j
#pragma unroll
        for (int mr = 0; mr < 2; mr++) {
#pragma unroll
            for (int half = 0; half < 2; half++) {
                int i_row = wr * 32 + mr * 16 + half * 8 + grp;    // 0..63
                int k = 2 * i_row + j;
#pragma unroll
                for (int nt = 0; nt < 4; nt++) {
                    int c = wc * 32 + nt * 8 + tid4 * 2;
                    __half2 hv = __float22half2_rn(make_float2(
                        acc[mr][nt][half * 2 + 0], acc[mr][nt][half * 2 + 1]));
                    *(uint32_t*)(smb + PP_IMG + sw_off(k, c >> 3) + tid4 * 4) = *(uint32_t*)&hv;
                }
            }
        }
    }
    __syncthreads();

    // coalesced bulk store: 2048 float4 = 32KB
    float4* dst = (float4*)(g_Pimg + (size_t)(m * NN + n) * 16384);
    const float4* src = (const float4*)(smb + PP_IMG);
#pragma unroll
    for (int i = 0; i < 8; i++)
        dst[i * 256 + tid] = src[i * 256 + tid];
}

// ---------------- kernel 0b: W image (fp16, 128B-row swizzle) ----------------
__global__ void prep_W_kernel(const float* __restrict__ outW) {
    int tid = threadIdx.x;
    char* gbase = (char*)g_Wimg;
#pragma unroll
    for (int it = 0; it < 16; it++) {
        int idx = it * 256 + tid;          // 4096 fp16-pair jobs
        int k = idx >> 5, n2 = idx & 31;
        float2 v = *(const float2*)(outW + k * DMOUT + 2 * n2);
        __half2 h = __float22half2_rn(v);
        uint32_t off = sw_off64(k, n2 >> 2) + (uint32_t)(n2 & 3) * 4u;
        *(uint32_t*)(gbase + off) = *(uint32_t*)&h;
    }
}

// ---------------- fused kernel (R9 form, unchanged) ----------------
#define OFF_Bb 49152
#define OFF_QKV 81920
#define QKV_OFF(m, g, t) (OFF_QKV + (((m) * G8 + (g)) * TT + (t)) * 260)
#define SMEMF_TOTAL 231680

__global__ __launch_bounds__(512, 1) void fused_kernel(
    const float* __restrict__ query, const float* __restrict__ key_,
    const float* __restrict__ value,
    const float* __restrict__ outb,
    float* __restrict__ out, float* __restrict__ attn_out, int write_attn) {
    extern __shared__ float smf[];
    char* smb = (char*)smf;
    const uint32_t sbase = smem_u32(smb);

    const int n = blockIdx.x;
    const int b0 = blockIdx.y * G8;
    const int tid = threadIdx.x, wid = tid >> 5, lane = tid & 31;
    const int wr = wid >> 2, wc = wid & 3;        // warp grid 4(M) x 4(N)
    const int grp = lane >> 2, tid4 = lane & 3;
    const int lq = lane & 7, qq = lane >> 3;

    // ===== three projections (M=192 = 8 batches x 24) =====
    for (int m = 0; m < 3; m++) {
        if (m) __syncthreads();
        {
            const char* bs = (const char*)(g_Pimg + (size_t)(m * NN + n) * 16384);
            uint32_t bd = sbase + OFF_Bb;
#pragma unroll
            for (int i = 0; i < 4; i++) {
                int c = i * 512 + tid;
                CP_ASYNC16(bd + c * 16, bs + c * 16);
            }
            CP_COMMIT();
        }
        {
            const float* x = (m == 0) ? query : ((m == 1) ? key_ : value);
#pragma unroll
            for (int it = 0; it < 12; it++) {
                int idx = it * 512 + tid;
                int r = idx >> 5, c4 = idx & 31;
                int g = r / TT, t = r - g * TT;
                float4 v = *(const float4*)(x + (((size_t)(b0 + g) * NN + n) * TT + t) * EE + 4 * c4);
                __half2 p01 = __float22half2_rn(make_float2(v.x, v.y));
                __half2 p23 = __float22half2_rn(make_float2(v.z, v.w));
                uint2 pk;
                pk.x = *(uint32_t*)&p01; pk.y = *(uint32_t*)&p23;
                uint32_t off = sw_off(r, c4 >> 1) + (uint32_t)(c4 & 1) * 8u;
                *(uint2*)(smb + off) = pk;
            }
        }
        CP_WAIT0();
        __syncthreads();

        float acc[3][4][4];
#pragma unroll
        for (int mr = 0; mr < 3; mr++)
#pragma unroll
            for (int nt = 0; nt < 4; nt++)
#pragma unroll
                for (int i = 0; i < 4; i++) acc[mr][nt][i] = 0.f;

#pragma unroll
        for (int kc = 0; kc < 8; kc++) {
            uint32_t a[3][4];
#pragma unroll
            for (int mr = 0; mr < 3; mr++) {
                int r = wr * 48 + mr * 16 + lq + (qq & 1) * 8;
                int ci = kc * 2 + (qq >> 1);
                ldsm_x4(a[mr], sbase + sw_off(r, ci));
            }
            uint32_t bf[4][2];
#pragma unroll
            for (int p = 0; p < 2; p++) {
                int r = kc * 16 + lq + (qq & 1) * 8;
                int ci = wc * 4 + p * 2 + (qq >> 1);
                uint32_t t4[4];
                ldsm_x4_t(t4, sbase + OFF_Bb + sw_off(r, ci));
                bf[2 * p][0] = t4[0]; bf[2 * p][1] = t4[1];
                bf[2 * p + 1][0] = t4[2]; bf[2 * p + 1][1] = t4[3];
            }
#pragma unroll
            for (int mr = 0; mr < 3; mr++)
#pragma unroll
                for (int nt = 0; nt < 4; nt++)
                    mma_f16(acc[mr][nt], a[mr], bf[nt]);
        }

        // epilogue: relu -> qkv fp16
#pragma unroll
        for (int mr = 0; mr < 3; mr++) {
#pragma unroll
            for (int half = 0; half < 2; half++) {
                int row = wr * 48 + mr * 16 + half * 8 + grp;
                int g = row / TT, t = row - g * TT;
                char* dst = smb + QKV_OFF(m, g, t);
#pragma unroll
                for (int nt = 0; nt < 4; nt++) {
                    int col = wc * 32 + nt * 8 + tid4 * 2;
                    __half2 hv = __float22half2_rn(make_float2(
                        fmaxf(acc[mr][nt][half * 2 + 0], 0.f),
                        fmaxf(acc[mr][nt][half * 2 + 1], 0.f)));
                    *(uint32_t*)(dst + col * 2) = *(uint32_t*)&hv;
                }
            }
        }
    }
    __syncthreads();      // qkv done; A + B regions free

    // W image async copy into B region (overlaps attention)
    {
        const char* ws = (const char*)g_Wimg;
        CP_ASYNC16(sbase + OFF_Bb + tid * 16, ws + tid * 16);
        CP_ASYNC16(sbase + OFF_Bb + (512 + tid) * 16, ws + (512 + tid) * 16);
        CP_COMMIT();
    }

    // ===== attention: 4 reps x (2 batch-slots x 8 heads), sync-free, rolled =====
    const int slot = wid >> 3, h = wid & 7;
    const int t = lane;
#pragma unroll 1
    for (int rep = 0; rep < 4; rep++) {
        const int gg = rep * 2 + slot;
        const long bn = (long)(b0 + gg) * NN + n;
        if (t < TT) {
            float qr[HD];
            {
                const uint32_t* qp = (const uint32_t*)(smb + QKV_OFF(0, gg, t) + h * 32);
#pragma unroll
                for (int e2 = 0; e2 < 8; e2++) {
                    uint32_t u = qp[e2];
                    float2 f = __half22float2(*(const __half2*)&u);
                    qr[2 * e2] = f.x; qr[2 * e2 + 1] = f.y;
                }
            }
            float sc[TT];
#pragma unroll
            for (int s = 0; s < TT; s++) {
                const uint32_t* kp = (const uint32_t*)(smb + QKV_OFF(1, gg, s) + h * 32);
                float a = 0.f;
#pragma unroll
                for (int e2 = 0; e2 < 8; e2++) {
                    uint32_t u = kp[e2];
                    float2 f = __half22float2(*(const __half2*)&u);
                    a += qr[2 * e2] * f.x + qr[2 * e2 + 1] * f.y;
                }
                sc[s] = a;
            }
            const float scale = 0.25f;
            float mx = -1e30f;
#pragma unroll
            for (int s = 0; s < TT; s++) if (s <= t) mx = fmaxf(mx, sc[s] * scale);
            float sum = 0.f, pr[TT];
#pragma unroll
            for (int s = 0; s < TT; s++) {
                float p = (s <= t) ? __expf(sc[s] * scale - mx) : 0.f;
                pr[s] = p; sum += p;
            }
            float inv = 1.f / sum;
#pragma unroll
            for (int s = 0; s < TT; s++) pr[s] *= inv;

            float o[HD];
#pragma unroll
            for (int d = 0; d < HD; d++) o[d] = 0.f;
#pragma unroll
            for (int s = 0; s < TT; s++) {
                const uint32_t* vp = (const uint32_t*)(smb + QKV_OFF(2, gg, s) + h * 32);
                float pv = pr[s];
#pragma unroll
                for (int d2 = 0; d2 < 8; d2++) {
                    uint32_t u = vp[d2];
                    float2 f = __half22float2(*(const __half2*)&u);
                    o[2 * d2] += pv * f.x; o[2 * d2 + 1] += pv * f.y;
                }
            }
            // sO as fp16 into A image: row = gg*24 + t, cols h*16..h*16+15
            {
                int row = gg * TT + t;
                uint4 pk0, pk1;
                __half2 v0 = __float22half2_rn(make_float2(o[0], o[1]));
                __half2 v1 = __float22half2_rn(make_float2(o[2], o[3]));
                __half2 v2 = __float22half2_rn(make_float2(o[4], o[5]));
                __half2 v3 = __float22half2_rn(make_float2(o[6], o[7]));
                __half2 v4 = __float22half2_rn(make_float2(o[8], o[9]));
                __half2 v5 = __float22half2_rn(make_float2(o[10], o[11]));
                __half2 v6 = __float22half2_rn(make_float2(o[12], o[13]));
                __half2 v7 = __float22half2_rn(make_float2(o[14], o[15]));
                pk0.x = *(uint32_t*)&v0; pk0.y = *(uint32_t*)&v1;
                pk0.z = *(uint32_t*)&v2; pk0.w = *(uint32_t*)&v3;
                pk1.x = *(uint32_t*)&v4; pk1.y = *(uint32_t*)&v5;
                pk1.z = *(uint32_t*)&v6; pk1.w = *(uint32_t*)&v7;
                *(uint4*)(smb + sw_off(row, h * 2))     = pk0;
                *(uint4*)(smb + sw_off(row, h * 2 + 1)) = pk1;
            }
            if (write_attn) {
                float* ab = attn_out + (((bn * HH) + h) * TT + t) * TT;
#pragma unroll
                for (int s4 = 0; s4 < TT / 4; s4++)
                    ((float4*)ab)[s4] = make_float4(pr[4 * s4], pr[4 * s4 + 1], pr[4 * s4 + 2], pr[4 * s4 + 3]);
            }
        }
    }
    CP_WAIT0();
    __syncthreads();      // sO image complete, W image ready

    // ===== output projection: (192x128) @ (128x64) mma, bias+relu =====
    {
        float acc[3][2][4];
#pragma unroll
        for (int mr = 0; mr < 3; mr++)
#pragma unroll
            for (int nt = 0; nt < 2; nt++)
#pragma unroll
                for (int i = 0; i < 4; i++) acc[mr][nt][i] = 0.f;

#pragma unroll
        for (int kc = 0; kc < 8; kc++) {
            uint32_t a[3][4];
#pragma unroll
            for (int mr = 0; mr < 3; mr++) {
                int r = wr * 48 + mr * 16 + lq + (qq & 1) * 8;
                int ci = kc * 2 + (qq >> 1);
                ldsm_x4(a[mr], sbase + sw_off(r, ci));
            }
            uint32_t bf[2][2];
            {
                int r = kc * 16 + lq + (qq & 1) * 8;
                int ci = wc * 2 + (qq >> 1);
                uint32_t t4[4];
                ldsm_x4_t(t4, sbase + OFF_Bb + sw_off64(r, ci));
                bf[0][0] = t4[0]; bf[0][1] = t4[1];
                bf[1][0] = t4[2]; bf[1][1] = t4[3];
            }
#pragma unroll
            for (int mr = 0; mr < 3; mr++)
#pragma unroll
                for (int nt = 0; nt < 2; nt++)
                    mma_f16(acc[mr][nt], a[mr], bf[nt]);
        }

        float2 bias[2];
#pragma unroll
        for (int nt = 0; nt < 2; nt++) {
            int col = wc * 16 + nt * 8 + tid4 * 2;
            bias[nt] = make_float2(__ldg(outb + col), __ldg(outb + col + 1));
        }
#pragma unroll
        for (int mr = 0; mr < 3; mr++) {
#pragma unroll
            for (int half = 0; half < 2; half++) {
                int row = wr * 48 + mr * 16 + half * 8 + grp;
                int g = row / TT, t2 = row - g * TT;
                const long bn = (long)(b0 + g) * NN + n;
                float* op = out + ((bn * TT) + t2) * DMOUT;
#pragma unroll
                for (int nt = 0; nt < 2; nt++) {
                    int col = wc * 16 + nt * 8 + tid4 * 2;
                    *(float2*)(op + col) = make_float2(
                        fmaxf(acc[mr][nt][half * 2 + 0] + bias[nt].x, 0.f),
                        fmaxf(acc[mr][nt][half * 2 + 1] + bias[nt].y, 0.f));
                }
            }
        }
    }
}

// ---------------- launch ----------------
extern "C" void kernel_launch(void* const* d_in, const int* in_sizes, int n_in,
                              void* d_out, int out_size) {
    const float* query = (const float*)d_in[0];
    const float* key_  = (const float*)d_in[1];
    const float* value = (const float*)d_in[2];
    const float* qp1 = (const float*)d_in[4];
    const float* qp2 = (const float*)d_in[5];
    const float* kp1 = (const float*)d_in[6];
    const float* kp2 = (const float*)d_in[7];
    const float* vp1 = (const float*)d_in[8];
    const float* vp2 = (const float*)d_in[9];
    const float* outW = (const float*)d_in[10];
    const float* outb = (const float*)d_in[11];

    float* out = (float*)d_out;
    int write_attn = (out_size >= OUT_N + ATTN_N) ? 1 : 0;

    static int attr_done = 0;
    if (!attr_done) {
        cudaFuncSetAttribute(prep_P_kernel, cudaFuncAttributeMaxDynamicSharedMemorySize, PP_SMEM);
        cudaFuncSetAttribute(fused_kernel, cudaFuncAttributeMaxDynamicSharedMemorySize, SMEMF_TOTAL);
        attr_done = 1;
    }

    prep_P_kernel<<<dim3(NN, 3), 256, PP_SMEM>>>(qp1, qp2, kp1, kp2, vp1, vp2);
    prep_W_kernel<<<1, 256>>>(outW);
    fused_kernel<<<dim3(NN, BB / G8), 512, SMEMF_TOTAL>>>(
        query, key_, value, outb, out, out + OUT_N, write_attn);
}

// round 11
// speedup vs baseline: 2.1547x; 1.0210x over previous
#include <cuda_runtime.h>
#include <cuda_fp16.h>
#include <cuda_bf16.h>
#include <cstdint>

// ---------------- problem constants ----------------
#define BB 32
#define NN 207
#define TT 24
#define EE 128
#define HH 8
#define HD 16
#define DMOUT 64
#define MM 32
#define G8 8                         // batches per fused block

#define OUT_N (BB * NN * TT * DMOUT)
#define ATTN_N (BB * NN * HH * TT * TT)

// P images: per (m,n): 128 k-rows x 128 n-cols fp16, swizzled (32KB)
__device__ __align__(16) __half g_Pimg[(size_t)3 * NN * 16384];
// W image: 128 k-rows x 64 n-cols fp16, 128B-row swizzle (16KB)
__device__ __align__(16) __half g_Wimg[8192];

// ---------------- helpers ----------------
__device__ __forceinline__ uint32_t smem_u32(const void* p) {
    uint32_t a;
    asm("{ .reg .u64 t; cvta.to.shared.u64 t, %1; cvt.u32.u64 %0, t; }" : "=r"(a) : "l"(p));
    return a;
}
// swizzled byte offset: 256B rows, 16B chunks ci 0..15
__device__ __forceinline__ uint32_t sw_off(int r, int ci) {
    return (uint32_t)r * 256u + (uint32_t)((ci ^ (r & 7)) << 4);
}
// swizzled byte offset: 128B rows, 16B chunks ci 0..7
__device__ __forceinline__ uint32_t sw_off64(int r, int ci) {
    return (uint32_t)r * 128u + (uint32_t)((ci ^ (r & 7)) << 4);
}
__device__ __forceinline__ void ldsm_x4(uint32_t* r, uint32_t addr) {
    asm volatile("ldmatrix.sync.aligned.m8n8.x4.shared.b16 {%0,%1,%2,%3}, [%4];"
                 : "=r"(r[0]), "=r"(r[1]), "=r"(r[2]), "=r"(r[3]) : "r"(addr));
}
__device__ __forceinline__ void ldsm_x4_t(uint32_t* r, uint32_t addr) {
    asm volatile("ldmatrix.sync.aligned.m8n8.x4.trans.shared.b16 {%0,%1,%2,%3}, [%4];"
                 : "=r"(r[0]), "=r"(r[1]), "=r"(r[2]), "=r"(r[3]) : "r"(addr));
}
__device__ __forceinline__ void mma_f16(float* d, const uint32_t* a, const uint32_t* b) {
    asm volatile("mma.sync.aligned.m16n8k16.row.col.f32.f16.f16.f32 "
                 "{%0,%1,%2,%3}, {%4,%5,%6,%7}, {%8,%9}, {%0,%1,%2,%3};"
                 : "+f"(d[0]), "+f"(d[1]), "+f"(d[2]), "+f"(d[3])
                 : "r"(a[0]), "r"(a[1]), "r"(a[2]), "r"(a[3]), "r"(b[0]), "r"(b[1]));
}
__device__ __forceinline__ void mma_bf16(float* d, const uint32_t* a, const uint32_t* b) {
    asm volatile("mma.sync.aligned.m16n8k16.row.col.f32.bf16.bf16.f32 "
                 "{%0,%1,%2,%3}, {%4,%5,%6,%7}, {%8,%9}, {%0,%1,%2,%3};"
                 : "+f"(d[0]), "+f"(d[1]), "+f"(d[2]), "+f"(d[3])
                 : "r"(a[0]), "r"(a[1]), "r"(a[2]), "r"(a[3]), "r"(b[0]), "r"(b[1]));
}
#define CP_ASYNC16(dst, src) \
    asm volatile("cp.async.cg.shared.global [%0], [%1], 16;" :: "r"(dst), "l"(src))
#define CP_COMMIT() asm volatile("cp.async.commit_group;")
#define CP_WAIT0()  asm volatile("cp.async.wait_group 0;")

__device__ __forceinline__ uint32_t pack_bf16(float x, float y) {
    __nv_bfloat16 h0 = __float2bfloat16(x);
    __nv_bfloat16 h1 = __float2bfloat16(y);
    return (uint32_t)__bfloat16_as_ushort(h0) | ((uint32_t)__bfloat16_as_ushort(h1) << 16);
}

// ---------------- kernel 0: P images via tensor cores (bf16 3-pass split) ----------------
#define PP_AL   16384
#define PP_B    32768
#define PP_IMG  65536
#define PP_SMEM 98304

__global__ __launch_bounds__(256, 2) void prep_P_kernel(
    const float* __restrict__ qp1, const float* __restrict__ qp2,
    const float* __restrict__ kp1, const float* __restrict__ kp2,
    const float* __restrict__ vp1, const float* __restrict__ vp2) {
    extern __shared__ float sm0[];
    char* smb = (char*)sm0;
    const uint32_t sbase = smem_u32(smb);

    const int n = blockIdx.x, m = blockIdx.y, tid = threadIdx.x;
    const int wid = tid >> 5, lane = tid & 31;
    const int wr = wid >> 2, wc = wid & 3;       // warp grid 2(M) x 4(N)
    const int grp = lane >> 2, tid4 = lane & 3;
    const int lq = lane & 7, qq = lane >> 3;

    const float* p1 = (m == 0) ? qp1 : ((m == 1) ? kp1 : vp1);
    const float* p2 = (m == 0) ? qp2 : ((m == 1) ? kp2 : vp2);

    {
        const float* p1b = p1 + (size_t)n * 2048;
#pragma unroll
        for (int it = 0; it < 4; it++) {
            int idx2 = it * 256 + tid;
            int r = idx2 >> 4, cp = idx2 & 15;
            float2 v = *(const float2*)(p1b + r * 32 + 2 * cp);
            float hx = __bfloat162float(__float2bfloat16(v.x));
            float hy = __bfloat162float(__float2bfloat16(v.y));
            uint32_t off = sw_off(r, cp >> 2) + (uint32_t)(cp & 3) * 4u;
            *(uint32_t*)(smb + off)         = pack_bf16(v.x, v.y);
            *(uint32_t*)(smb + PP_AL + off) = pack_bf16(v.x - hx, v.y - hy);
        }
    }
    {
#pragma unroll
        for (int it = 0; it < 16; it++) {
            int idx2 = it * 256 + tid;
            int r = idx2 >> 7, cp = idx2 & 127;
            float2 v = *(const float2*)(p2 + r * 256 + 2 * cp);
            int jj = cp >> 6, lcp = cp & 63;
            float hx = __bfloat162float(__float2bfloat16(v.x));
            float hy = __bfloat162float(__float2bfloat16(v.y));
            uint32_t off = sw_off(r, lcp >> 2) + (uint32_t)(lcp & 3) * 4u;
            char* bb = smb + PP_B + jj * 16384;
            *(uint32_t*)(bb + off)        = pack_bf16(v.x, v.y);
            *(uint32_t*)(bb + 8192 + off) = pack_bf16(v.x - hx, v.y - hy);
        }
    }
    __syncthreads();

#pragma unroll
    for (int j = 0; j < 2; j++) {
        float acc[2][4][4];
#pragma unroll
        for (int mr = 0; mr < 2; mr++)
#pragma unroll
            for (int nt = 0; nt < 4; nt++)
#pragma unroll
                for (int i = 0; i < 4; i++) acc[mr][nt][i] = 0.f;

        const uint32_t Ao[3] = {0u, PP_AL, 0u};
        const uint32_t Bo[3] = {0u, 0u, 8192u};
#pragma unroll
        for (int pass = 0; pass < 3; pass++) {
            const uint32_t aB = sbase + Ao[pass];
            const uint32_t bB = sbase + PP_B + (uint32_t)j * 16384u + Bo[pass];
#pragma unroll
            for (int kc = 0; kc < 2; kc++) {
                uint32_t a[2][4];
#pragma unroll
                for (int mr = 0; mr < 2; mr++) {
                    int r = wr * 32 + mr * 16 + lq + (qq & 1) * 8;
                    int ci = kc * 2 + (qq >> 1);
                    ldsm_x4(a[mr], aB + sw_off(r, ci));
                }
                uint32_t bf[4][2];
#pragma unroll
                for (int p = 0; p < 2; p++) {
                    int r = kc * 16 + lq + (qq & 1) * 8;
                    int ci = wc * 4 + p * 2 + (qq >> 1);
                    uint32_t t4[4];
                    ldsm_x4_t(t4, bB + sw_off(r, ci));
                    bf[2 * p][0] = t4[0]; bf[2 * p][1] = t4[1];
                    bf[2 * p + 1][0] = t4[2]; bf[2 * p + 1][1] = t4[3];
                }
#pragma unroll
                for (int mr = 0; mr < 2; mr++)
#pragma unroll
                    for (int nt = 0; nt < 4; nt++)
                        mma_bf16(acc[mr][nt], a[mr], bf[nt]);
            }
        }
#pragma unroll
        for (int mr = 0; mr < 2; mr++) {
#pragma unroll
            for (int half = 0; half < 2; half++) {
                int i_row = wr * 32 + mr * 16 + half * 8 + grp;
                int k = 2 * i_row + j;
#pragma unroll
                for (int nt = 0; nt < 4; nt++) {
                    int c = wc * 32 + nt * 8 + tid4 * 2;
                    __half2 hv = __float22half2_rn(make_float2(
                        acc[mr][nt][half * 2 + 0], acc[mr][nt][half * 2 + 1]));
                    *(uint32_t*)(smb + PP_IMG + sw_off(k, c >> 3) + tid4 * 4) = *(uint32_t*)&hv;
                }
            }
        }
    }
    __syncthreads();

    float4* dst = (float4*)(g_Pimg + (size_t)(m * NN + n) * 16384);
    const float4* src = (const float4*)(smb + PP_IMG);
#pragma unroll
    for (int i = 0; i < 8; i++)
        dst[i * 256 + tid] = src[i * 256 + tid];
}

// ---------------- kernel 0b: W image (fp16, 128B-row swizzle) ----------------
__global__ void prep_W_kernel(const float* __restrict__ outW) {
    int tid = threadIdx.x;
    char* gbase = (char*)g_Wimg;
#pragma unroll
    for (int it = 0; it < 16; it++) {
        int idx = it * 256 + tid;
        int k = idx >> 5, n2 = idx & 31;
        float2 v = *(const float2*)(outW + k * DMOUT + 2 * n2);
        __half2 h = __float22half2_rn(v);
        uint32_t off = sw_off64(k, n2 >> 2) + (uint32_t)(n2 & 3) * 4u;
        *(uint32_t*)(gbase + off) = *(uint32_t*)&h;
    }
}

// ---------------- fused kernel ----------------
// smem bytes:
//  [A 0..49152)      192x128 fp16 swizzled (X during each proj GEMM; q image, then sO, after)
//  [B 49152..81920)  P image during proj; W image (16KB) after
//  [KV 81920..181760)  fp16 [km in {K,V}][g][t] rows of 260B
//  [KVF 181760..230912) fp32 staged K,V for the 2 active batches: [slot][km][24][128]
#define OFF_Bb 49152
#define OFF_KV 81920
#define KV_OFF(km, g, t) (OFF_KV + (((km) * G8 + (g)) * TT + (t)) * 260)
#define OFF_KVF 181760
#define SMEMF_TOTAL 230912

__global__ __launch_bounds__(512, 1) void fused_kernel(
    const float* __restrict__ query, const float* __restrict__ key_,
    const float* __restrict__ value,
    const float* __restrict__ outb,
    float* __restrict__ out, float* __restrict__ attn_out, int write_attn) {
    extern __shared__ float smf[];
    char* smb = (char*)smf;
    const uint32_t sbase = smem_u32(smb);

    const int n = blockIdx.x;
    const int b0 = blockIdx.y * G8;
    const int tid = threadIdx.x, wid = tid >> 5, lane = tid & 31;
    const int wr = wid >> 2, wc = wid & 3;        // warp grid 4(M) x 4(N)
    const int grp = lane >> 2, tid4 = lane & 3;
    const int lq = lane & 7, qq = lane >> 3;

    // ===== three projections, order k, v, q (q epilogue overwrites A image) =====
    for (int mi = 0; mi < 3; mi++) {
        const int m = (mi + 1) % 3;               // 1, 2, 0
        if (mi) __syncthreads();
        {
            const char* bs = (const char*)(g_Pimg + (size_t)(m * NN + n) * 16384);
            uint32_t bd = sbase + OFF_Bb;
#pragma unroll
            for (int i = 0; i < 4; i++) {
                int c = i * 512 + tid;
                CP_ASYNC16(bd + c * 16, bs + c * 16);
            }
            CP_COMMIT();
        }
        {
            const float* x = (m == 0) ? query : ((m == 1) ? key_ : value);
#pragma unroll
            for (int it = 0; it < 12; it++) {
                int idx = it * 512 + tid;
                int r = idx >> 5, c4 = idx & 31;
                int g = r / TT, t = r - g * TT;
                float4 v = *(const float4*)(x + (((size_t)(b0 + g) * NN + n) * TT + t) * EE + 4 * c4);
                __half2 p01 = __float22half2_rn(make_float2(v.x, v.y));
                __half2 p23 = __float22half2_rn(make_float2(v.z, v.w));
                uint2 pk;
                pk.x = *(uint32_t*)&p01; pk.y = *(uint32_t*)&p23;
                uint32_t off = sw_off(r, c4 >> 1) + (uint32_t)(c4 & 1) * 8u;
                *(uint2*)(smb + off) = pk;
            }
        }
        CP_WAIT0();
        __syncthreads();

        float acc[3][4][4];
#pragma unroll
        for (int mr = 0; mr < 3; mr++)
#pragma unroll
            for (int nt = 0; nt < 4; nt++)
#pragma unroll
                for (int i = 0; i < 4; i++) acc[mr][nt][i] = 0.f;

#pragma unroll
        for (int kc = 0; kc < 8; kc++) {
            uint32_t a[3][4];
#pragma unroll
            for (int mr = 0; mr < 3; mr++) {
                int r = wr * 48 + mr * 16 + lq + (qq & 1) * 8;
                int ci = kc * 2 + (qq >> 1);
                ldsm_x4(a[mr], sbase + sw_off(r, ci));
            }
            uint32_t bf[4][2];
#pragma unroll
            for (int p = 0; p < 2; p++) {
                int r = kc * 16 + lq + (qq & 1) * 8;
                int ci = wc * 4 + p * 2 + (qq >> 1);
                uint32_t t4[4];
                ldsm_x4_t(t4, sbase + OFF_Bb + sw_off(r, ci));
                bf[2 * p][0] = t4[0]; bf[2 * p][1] = t4[1];
                bf[2 * p + 1][0] = t4[2]; bf[2 * p + 1][1] = t4[3];
            }
#pragma unroll
            for (int mr = 0; mr < 3; mr++)
#pragma unroll
                for (int nt = 0; nt < 4; nt++)
                    mma_f16(acc[mr][nt], a[mr], bf[nt]);
        }

        // epilogue
        if (m == 0) {
            __syncthreads();      // all mma reads of A (X_query) done before overwrite
#pragma unroll
            for (int mr = 0; mr < 3; mr++) {
#pragma unroll
                for (int half = 0; half < 2; half++) {
                    int row = wr * 48 + mr * 16 + half * 8 + grp;
#pragma unroll
                    for (int nt = 0; nt < 4; nt++) {
                        int col = wc * 32 + nt * 8 + tid4 * 2;
                        __half2 hv = __float22half2_rn(make_float2(
                            fmaxf(acc[mr][nt][half * 2 + 0], 0.f),
                            fmaxf(acc[mr][nt][half * 2 + 1], 0.f)));
                        *(uint32_t*)(smb + sw_off(row, col >> 3) + (col & 7) * 2) = *(uint32_t*)&hv;
                    }
                }
            }
        } else {
#pragma unroll
            for (int mr = 0; mr < 3; mr++) {
#pragma unroll
                for (int half = 0; half < 2; half++) {
                    int row = wr * 48 + mr * 16 + half * 8 + grp;
                    int g = row / TT, t = row - g * TT;
                    char* dst = smb + KV_OFF(m - 1, g, t);
#pragma unroll
                    for (int nt = 0; nt < 4; nt++) {
                        int col = wc * 32 + nt * 8 + tid4 * 2;
                        __half2 hv = __float22half2_rn(make_float2(
                            fmaxf(acc[mr][nt][half * 2 + 0], 0.f),
                            fmaxf(acc[mr][nt][half * 2 + 1], 0.f)));
                        *(uint32_t*)(dst + col * 2) = *(uint32_t*)&hv;
                    }
                }
            }
        }
    }
    __syncthreads();      // q image + K,V complete

    // W image async copy into B region (overlaps attention)
    {
        const char* ws = (const char*)g_Wimg;
        CP_ASYNC16(sbase + OFF_Bb + tid * 16, ws + tid * 16);
        CP_ASYNC16(sbase + OFF_Bb + (512 + tid) * 16, ws + (512 + tid) * 16);
        CP_COMMIT();
    }

    // ===== attention: 4 reps x (2 batch-slots x 8 heads), staged fp32 K/V =====
    const int slot = wid >> 3, h = wid & 7;
    const int t = lane;
#pragma unroll 1
    for (int rep = 0; rep < 4; rep++) {
        if (rep) __syncthreads();    // prev rep done reading KVF
        // stage K,V fp32 for this rep's two batches: 6144 half2 -> float2 jobs
#pragma unroll
        for (int it = 0; it < 12; it++) {
            int idx = it * 512 + tid;
            int e2 = idx & 63;
            int rem = idx >> 6;                  // (sl*2+km)*24 + t2, 0..95
            int t2 = rem % 24;
            int sk = rem / 24;                   // sl*2+km
            int sl2 = sk >> 1, km = sk & 1;
            uint32_t u = *(const uint32_t*)(smb + KV_OFF(km, rep * 2 + sl2, t2) + e2 * 4);
            float2 f = __half22float2(*(const __half2*)&u);
            *(float2*)(smb + OFF_KVF + (size_t)idx * 8) = f;
        }
        __syncthreads();

        const int gg = rep * 2 + slot;
        const long bn = (long)(b0 + gg) * NN + n;
        if (t < TT) {
            const int row = gg * TT + t;
            float qr[HD];
            {
                uint4 qa = *(const uint4*)(smb + sw_off(row, h * 2));
                uint4 qb = *(const uint4*)(smb + sw_off(row, h * 2 + 1));
                uint32_t qw[8] = {qa.x, qa.y, qa.z, qa.w, qb.x, qb.y, qb.z, qb.w};
#pragma unroll
                for (int e2 = 0; e2 < 8; e2++) {
                    float2 f = __half22float2(*(const __half2*)&qw[e2]);
                    qr[2 * e2] = f.x; qr[2 * e2 + 1] = f.y;
                }
            }
            const float* kbase = smf + OFF_KVF / 4 + (slot * 2 + 0) * (TT * EE) + h * HD;
            const float* vbase = smf + OFF_KVF / 4 + (slot * 2 + 1) * (TT * EE) + h * HD;

            float sc[TT];
#pragma unroll
            for (int s = 0; s < TT; s++) {
                const float* kr = kbase + s * EE;
                float a = 0.f;
#pragma unroll
                for (int e2 = 0; e2 < 8; e2++) {
                    float2 f = *(const float2*)(kr + 2 * e2);
                    a += qr[2 * e2] * f.x + qr[2 * e2 + 1] * f.y;
                }
                sc[s] = a;
            }
            const float scale = 0.25f;
            float mx = -1e30f;
#pragma unroll
            for (int s = 0; s < TT; s++) if (s <= t) mx = fmaxf(mx, sc[s] * scale);
            float sum = 0.f;
#pragma unroll
            for (int s = 0; s < TT; s++) {
                float p = (s <= t) ? __expf(sc[s] * scale - mx) : 0.f;
                sc[s] = p; sum += p;
            }
            float inv = 1.f / sum;
#pragma unroll
            for (int s = 0; s < TT; s++) sc[s] *= inv;

            float o[HD];
#pragma unroll
            for (int d = 0; d < HD; d++) o[d] = 0.f;
#pragma unroll
            for (int s = 0; s < TT; s++) {
                const float* vr = vbase + s * EE;
                float pv = sc[s];
#pragma unroll
                for (int d2 = 0; d2 < 8; d2++) {
                    float2 f = *(const float2*)(vr + 2 * d2);
                    o[2 * d2] += pv * f.x; o[2 * d2 + 1] += pv * f.y;
                }
            }
            // sO as fp16 into A image (overwrites this thread's q cols)
            {
                uint4 pk0, pk1;
                __half2 v0 = __float22half2_rn(make_float2(o[0], o[1]));
                __half2 v1 = __float22half2_rn(make_float2(o[2], o[3]));
                __half2 v2 = __float22half2_rn(make_float2(o[4], o[5]));
                __half2 v3 = __float22half2_rn(make_float2(o[6], o[7]));
                __half2 v4 = __float22half2_rn(make_float2(o[8], o[9]));
                __half2 v5 = __float22half2_rn(make_float2(o[10], o[11]));
                __half2 v6 = __float22half2_rn(make_float2(o[12], o[13]));
                __half2 v7 = __float22half2_rn(make_float2(o[14], o[15]));
                pk0.x = *(uint32_t*)&v0; pk0.y = *(uint32_t*)&v1;
                pk0.z = *(uint32_t*)&v2; pk0.w = *(uint32_t*)&v3;
                pk1.x = *(uint32_t*)&v4; pk1.y = *(uint32_t*)&v5;
                pk1.z = *(uint32_t*)&v6; pk1.w = *(uint32_t*)&v7;
                *(uint4*)(smb + sw_off(row, h * 2))     = pk0;
                *(uint4*)(smb + sw_off(row, h * 2 + 1)) = pk1;
            }
            if (write_attn) {
                float* ab = attn_out + (((bn * HH) + h) * TT + t) * TT;
#pragma unroll
                for (int s4 = 0; s4 < TT / 4; s4++)
                    ((float4*)ab)[s4] = make_float4(sc[4 * s4], sc[4 * s4 + 1], sc[4 * s4 + 2], sc[4 * s4 + 3]);
            }
        }
    }
    CP_WAIT0();
    __syncthreads();      // sO image complete, W image ready

    // ===== output projection: (192x128) @ (128x64) mma, bias+relu =====
    {
        float acc[3][2][4];
#pragma unroll
        for (int mr = 0; mr < 3; mr++)
#pragma unroll
            for (int nt = 0; nt < 2; nt++)
#pragma unroll
                for (int i = 0; i < 4; i++) acc[mr][nt][i] = 0.f;

#pragma unroll
        for (int kc = 0; kc < 8; kc++) {
            uint32_t a[3][4];
#pragma unroll
            for (int mr = 0; mr < 3; mr++) {
                int r = wr * 48 + mr * 16 + lq + (qq & 1) * 8;
                int ci = kc * 2 + (qq >> 1);
                ldsm_x4(a[mr], sbase + sw_off(r, ci));
            }
            uint32_t bf[2][2];
            {
                int r = kc * 16 + lq + (qq & 1) * 8;
                int ci = wc * 2 + (qq >> 1);
                uint32_t t4[4];
                ldsm_x4_t(t4, sbase + OFF_Bb + sw_off64(r, ci));
                bf[0][0] = t4[0]; bf[0][1] = t4[1];
                bf[1][0] = t4[2]; bf[1][1] = t4[3];
            }
#pragma unroll
            for (int mr = 0; mr < 3; mr++)
#pragma unroll
                for (int nt = 0; nt < 2; nt++)
                    mma_f16(acc[mr][nt], a[mr], bf[nt]);
        }

        float2 bias[2];
#pragma unroll
        for (int nt = 0; nt < 2; nt++) {
            int col = wc * 16 + nt * 8 + tid4 * 2;
            bias[nt] = make_float2(__ldg(outb + col), __ldg(outb + col + 1));
        }
#pragma unroll
        for (int mr = 0; mr < 3; mr++) {
#pragma unroll
            for (int half = 0; half < 2; half++) {
                int row = wr * 48 + mr * 16 + half * 8 + grp;
                int g = row / TT, t2 = row - g * TT;
                const long bn = (long)(b0 + g) * NN + n;
                float* op = out + ((bn * TT) + t2) * DMOUT;
#pragma unroll
                for (int nt = 0; nt < 2; nt++) {
                    int col = wc * 16 + nt * 8 + tid4 * 2;
                    *(float2*)(op + col) = make_float2(
                        fmaxf(acc[mr][nt][half * 2 + 0] + bias[nt].x, 0.f),
                        fmaxf(acc[mr][nt][half * 2 + 1] + bias[nt].y, 0.f));
                }
            }
        }
    }
}

// ---------------- launch ----------------
extern "C" void kernel_launch(void* const* d_in, const int* in_sizes, int n_in,
                              void* d_out, int out_size) {
    const float* query = (const float*)d_in[0];
    const float* key_  = (const float*)d_in[1];
    const float* value = (const float*)d_in[2];
    const float* qp1 = (const float*)d_in[4];
    const float* qp2 = (const float*)d_in[5];
    const float* kp1 = (const float*)d_in[6];
    const float* kp2 = (const float*)d_in[7];
    const float* vp1 = (const float*)d_in[8];
    const float* vp2 = (const float*)d_in[9];
    const float* outW = (const float*)d_in[10];
    const float* outb = (const float*)d_in[11];

    float* out = (float*)d_out;
    int write_attn = (out_size >= OUT_N + ATTN_N) ? 1 : 0;

    static int attr_done = 0;
    if (!attr_done) {
        cudaFuncSetAttribute(prep_P_kernel, cudaFuncAttributeMaxDynamicSharedMemorySize, PP_SMEM);
        cudaFuncSetAttribute(fused_kernel, cudaFuncAttributeMaxDynamicSharedMemorySize, SMEMF_TOTAL);
        attr_done = 1;
    }

    prep_P_kernel<<<dim3(NN, 3), 256, PP_SMEM>>>(qp1, qp2, kp1, kp2, vp1, vp2);
    prep_W_kernel<<<1, 256>>>(outW);
    fused_kernel<<<dim3(NN, BB / G8), 512, SMEMF_TOTAL>>>(
        query, key_, value, outb, out, out + OUT_N, write_attn);
}

// round 12
// speedup vs baseline: 2.4811x; 1.1515x over previous
#include <cuda_runtime.h>
#include <cuda_fp16.h>
#include <cuda_bf16.h>
#include <cstdint>

// ---------------- problem constants ----------------
#define BB 32
#define NN 207
#define TT 24
#define EE 128
#define HH 8
#define HD 16
#define DMOUT 64
#define MM 32
#define G4 4                         // batches per fused block

#define OUT_N (BB * NN * TT * DMOUT)
#define ATTN_N (BB * NN * HH * TT * TT)

// P images: per (m,n): 128 k-rows x 128 n-cols fp16, swizzled (32KB)
__device__ __align__(16) __half g_Pimg[(size_t)3 * NN * 16384];
// W image: 128 k-rows x 64 n-cols fp16, 128B-row swizzle (16KB)
__device__ __align__(16) __half g_Wimg[8192];

// ---------------- helpers ----------------
__device__ __forceinline__ uint32_t smem_u32(const void* p) {
    uint32_t a;
    asm("{ .reg .u64 t; cvta.to.shared.u64 t, %1; cvt.u32.u64 %0, t; }" : "=r"(a) : "l"(p));
    return a;
}
// swizzled byte offset: 256B rows, 16B chunks ci 0..15
__device__ __forceinline__ uint32_t sw_off(int r, int ci) {
    return (uint32_t)r * 256u + (uint32_t)((ci ^ (r & 7)) << 4);
}
// swizzled byte offset: 128B rows, 16B chunks ci 0..7
__device__ __forceinline__ uint32_t sw_off64(int r, int ci) {
    return (uint32_t)r * 128u + (uint32_t)((ci ^ (r & 7)) << 4);
}
__device__ __forceinline__ void ldsm_x4(uint32_t* r, uint32_t addr) {
    asm volatile("ldmatrix.sync.aligned.m8n8.x4.shared.b16 {%0,%1,%2,%3}, [%4];"
                 : "=r"(r[0]), "=r"(r[1]), "=r"(r[2]), "=r"(r[3]) : "r"(addr));
}
__device__ __forceinline__ void ldsm_x4_t(uint32_t* r, uint32_t addr) {
    asm volatile("ldmatrix.sync.aligned.m8n8.x4.trans.shared.b16 {%0,%1,%2,%3}, [%4];"
                 : "=r"(r[0]), "=r"(r[1]), "=r"(r[2]), "=r"(r[3]) : "r"(addr));
}
__device__ __forceinline__ void mma_f16(float* d, const uint32_t* a, const uint32_t* b) {
    asm volatile("mma.sync.aligned.m16n8k16.row.col.f32.f16.f16.f32 "
                 "{%0,%1,%2,%3}, {%4,%5,%6,%7}, {%8,%9}, {%0,%1,%2,%3};"
                 : "+f"(d[0]), "+f"(d[1]), "+f"(d[2]), "+f"(d[3])
                 : "r"(a[0]), "r"(a[1]), "r"(a[2]), "r"(a[3]), "r"(b[0]), "r"(b[1]));
}
__device__ __forceinline__ void mma_bf16(float* d, const uint32_t* a, const uint32_t* b) {
    asm volatile("mma.sync.aligned.m16n8k16.row.col.f32.bf16.bf16.f32 "
                 "{%0,%1,%2,%3}, {%4,%5,%6,%7}, {%8,%9}, {%0,%1,%2,%3};"
                 : "+f"(d[0]), "+f"(d[1]), "+f"(d[2]), "+f"(d[3])
                 : "r"(a[0]), "r"(a[1]), "r"(a[2]), "r"(a[3]), "r"(b[0]), "r"(b[1]));
}
#define CP_ASYNC16(dst, src) \
    asm volatile("cp.async.cg.shared.global [%0], [%1], 16;" :: "r"(dst), "l"(src))
#define CP_COMMIT() asm volatile("cp.async.commit_group;")
#define CP_WAIT0()  asm volatile("cp.async.wait_group 0;")

__device__ __forceinline__ uint32_t pack_bf16(float x, float y) {
    __nv_bfloat16 h0 = __float2bfloat16(x);
    __nv_bfloat16 h1 = __float2bfloat16(y);
    return (uint32_t)__bfloat16_as_ushort(h0) | ((uint32_t)__bfloat16_as_ushort(h1) << 16);
}

// ---------------- kernel 0: P images via tensor cores (bf16 3-pass split) ----------------
#define PP_AL   16384
#define PP_B    32768
#define PP_IMG  65536
#define PP_SMEM 98304

__global__ __launch_bounds__(256, 2) void prep_P_kernel(
    const float* __restrict__ qp1, const float* __restrict__ qp2,
    const float* __restrict__ kp1, const float* __restrict__ kp2,
    const float* __restrict__ vp1, const float* __restrict__ vp2) {
    extern __shared__ float sm0[];
    char* smb = (char*)sm0;
    const uint32_t sbase = smem_u32(smb);

    const int n = blockIdx.x, m = blockIdx.y, tid = threadIdx.x;
    const int wid = tid >> 5, lane = tid & 31;
    const int wr = wid >> 2, wc = wid & 3;       // warp grid 2(M) x 4(N)
    const int grp = lane >> 2, tid4 = lane & 3;
    const int lq = lane & 7, qq = lane >> 3;

    const float* p1 = (m == 0) ? qp1 : ((m == 1) ? kp1 : vp1);
    const float* p2 = (m == 0) ? qp2 : ((m == 1) ? kp2 : vp2);

    {
        const float* p1b = p1 + (size_t)n * 2048;
#pragma unroll
        for (int it = 0; it < 4; it++) {
            int idx2 = it * 256 + tid;
            int r = idx2 >> 4, cp = idx2 & 15;
            float2 v = *(const float2*)(p1b + r * 32 + 2 * cp);
            float hx = __bfloat162float(__float2bfloat16(v.x));
            float hy = __bfloat162float(__float2bfloat16(v.y));
            uint32_t off = sw_off(r, cp >> 2) + (uint32_t)(cp & 3) * 4u;
            *(uint32_t*)(smb + off)         = pack_bf16(v.x, v.y);
            *(uint32_t*)(smb + PP_AL + off) = pack_bf16(v.x - hx, v.y - hy);
        }
    }
    {
#pragma unroll
        for (int it = 0; it < 16; it++) {
            int idx2 = it * 256 + tid;
            int r = idx2 >> 7, cp = idx2 & 127;
            float2 v = *(const float2*)(p2 + r * 256 + 2 * cp);
            int jj = cp >> 6, lcp = cp & 63;
            float hx = __bfloat162float(__float2bfloat16(v.x));
            float hy = __bfloat162float(__float2bfloat16(v.y));
            uint32_t off = sw_off(r, lcp >> 2) + (uint32_t)(lcp & 3) * 4u;
            char* bb = smb + PP_B + jj * 16384;
            *(uint32_t*)(bb + off)        = pack_bf16(v.x, v.y);
            *(uint32_t*)(bb + 8192 + off) = pack_bf16(v.x - hx, v.y - hy);
        }
    }
    __syncthreads();

#pragma unroll
    for (int j = 0; j < 2; j++) {
        float acc[2][4][4];
#pragma unroll
        for (int mr = 0; mr < 2; mr++)
#pragma unroll
            for (int nt = 0; nt < 4; nt++)
#pragma unroll
                for (int i = 0; i < 4; i++) acc[mr][nt][i] = 0.f;

        const uint32_t Ao[3] = {0u, PP_AL, 0u};
        const uint32_t Bo[3] = {0u, 0u, 8192u};
#pragma unroll
        for (int pass = 0; pass < 3; pass++) {
            const uint32_t aB = sbase + Ao[pass];
            const uint32_t bB = sbase + PP_B + (uint32_t)j * 16384u + Bo[pass];
#pragma unroll
            for (int kc = 0; kc < 2; kc++) {
                uint32_t a[2][4];
#pragma unroll
                for (int mr = 0; mr < 2; mr++) {
                    int r = wr * 32 + mr * 16 + lq + (qq & 1) * 8;
                    int ci = kc * 2 + (qq >> 1);
                    ldsm_x4(a[mr], aB + sw_off(r, ci));
                }
                uint32_t bf[4][2];
#pragma unroll
                for (int p = 0; p < 2; p++) {
                    int r = kc * 16 + lq + (qq & 1) * 8;
                    int ci = wc * 4 + p * 2 + (qq >> 1);
                    uint32_t t4[4];
                    ldsm_x4_t(t4, bB + sw_off(r, ci));
                    bf[2 * p][0] = t4[0]; bf[2 * p][1] = t4[1];
                    bf[2 * p + 1][0] = t4[2]; bf[2 * p + 1][1] = t4[3];
                }
#pragma unroll
                for (int mr = 0; mr < 2; mr++)
#pragma unroll
                    for (int nt = 0; nt < 4; nt++)
                        mma_bf16(acc[mr][nt], a[mr], bf[nt]);
            }
        }
#pragma unroll
        for (int mr = 0; mr < 2; mr++) {
#pragma unroll
            for (int half = 0; half < 2; half++) {
                int i_row = wr * 32 + mr * 16 + half * 8 + grp;
                int k = 2 * i_row + j;
#pragma unroll
                for (int nt = 0; nt < 4; nt++) {
                    int c = wc * 32 + nt * 8 + tid4 * 2;
                    __half2 hv = __float22half2_rn(make_float2(
                        acc[mr][nt][half * 2 + 0], acc[mr][nt][half * 2 + 1]));
                    *(uint32_t*)(smb + PP_IMG + sw_off(k, c >> 3) + tid4 * 4) = *(uint32_t*)&hv;
                }
            }
        }
    }
    __syncthreads();

    float4* dst = (float4*)(g_Pimg + (size_t)(m * NN + n) * 16384);
    const float4* src = (const float4*)(smb + PP_IMG);
#pragma unroll
    for (int i = 0; i < 8; i++)
        dst[i * 256 + tid] = src[i * 256 + tid];
}

// ---------------- kernel 0b: W image (fp16, 128B-row swizzle) ----------------
__global__ void prep_W_kernel(const float* __restrict__ outW) {
    int tid = threadIdx.x;
    char* gbase = (char*)g_Wimg;
#pragma unroll
    for (int it = 0; it < 16; it++) {
        int idx = it * 256 + tid;
        int k = idx >> 5, n2 = idx & 31;
        float2 v = *(const float2*)(outW + k * DMOUT + 2 * n2);
        __half2 h = __float22half2_rn(v);
        uint32_t off = sw_off64(k, n2 >> 2) + (uint32_t)(n2 & 3) * 4u;
        *(uint32_t*)(gbase + off) = *(uint32_t*)&h;
    }
}

// ---------------- fused kernel: 4 batches per block, 2 CTAs/SM ----------------
// smem bytes per CTA (107,264 total):
//  [A 0..24576)      96x128 fp16 swizzled (X during proj; q image -> sO after)
//  [B 24576..57344)  P image during proj; W image (16KB) after
//  [KV 57344..107264) fp16 [km in {K,V}][g][t] rows of 260B
#define OFF_Bb 24576
#define OFF_KV 57344
#define KV_OFF(km, g, t) (OFF_KV + (((km) * G4 + (g)) * TT + (t)) * 260)
#define SMEMF_TOTAL 107264

__global__ __launch_bounds__(256, 2) void fused_kernel(
    const float* __restrict__ query, const float* __restrict__ key_,
    const float* __restrict__ value,
    const float* __restrict__ outb,
    float* __restrict__ out, float* __restrict__ attn_out, int write_attn) {
    extern __shared__ float smf[];
    char* smb = (char*)smf;
    const uint32_t sbase = smem_u32(smb);

    const int n = blockIdx.x;
    const int b0 = blockIdx.y * G4;
    const int tid = threadIdx.x, wid = tid >> 5, lane = tid & 31;
    const int wr = wid >> 2, wc = wid & 3;        // warp grid 2(M) x 4(N)
    const int grp = lane >> 2, tid4 = lane & 3;
    const int lq = lane & 7, qq = lane >> 3;

    // ===== three projections (M=96 = 4 batches x 24), order k, v, q =====
    for (int mi = 0; mi < 3; mi++) {
        const int m = (mi + 1) % 3;               // 1, 2, 0
        if (mi) __syncthreads();
        {
            const char* bs = (const char*)(g_Pimg + (size_t)(m * NN + n) * 16384);
            uint32_t bd = sbase + OFF_Bb;
#pragma unroll
            for (int i = 0; i < 8; i++) {
                int c = i * 256 + tid;
                CP_ASYNC16(bd + c * 16, bs + c * 16);
            }
            CP_COMMIT();
        }
        {
            const float* x = (m == 0) ? query : ((m == 1) ? key_ : value);
#pragma unroll
            for (int it = 0; it < 12; it++) {
                int idx = it * 256 + tid;          // 3072 float4 jobs
                int r = idx >> 5, c4 = idx & 31;
                int g = r / TT, t = r - g * TT;
                float4 v = *(const float4*)(x + (((size_t)(b0 + g) * NN + n) * TT + t) * EE + 4 * c4);
                __half2 p01 = __float22half2_rn(make_float2(v.x, v.y));
                __half2 p23 = __float22half2_rn(make_float2(v.z, v.w));
                uint2 pk;
                pk.x = *(uint32_t*)&p01; pk.y = *(uint32_t*)&p23;
                uint32_t off = sw_off(r, c4 >> 1) + (uint32_t)(c4 & 1) * 8u;
                *(uint2*)(smb + off) = pk;
            }
        }
        CP_WAIT0();
        __syncthreads();

        // GEMM 96 x 128 x 128, single pass fp16
        float acc[3][4][4];
#pragma unroll
        for (int mr = 0; mr < 3; mr++)
#pragma unroll
            for (int nt = 0; nt < 4; nt++)
#pragma unroll
                for (int i = 0; i < 4; i++) acc[mr][nt][i] = 0.f;

#pragma unroll
        for (int kc = 0; kc < 8; kc++) {
            uint32_t a[3][4];
#pragma unroll
            for (int mr = 0; mr < 3; mr++) {
                int r = wr * 48 + mr * 16 + lq + (qq & 1) * 8;
                int ci = kc * 2 + (qq >> 1);
                ldsm_x4(a[mr], sbase + sw_off(r, ci));
            }
            uint32_t bf[4][2];
#pragma unroll
            for (int p = 0; p < 2; p++) {
                int r = kc * 16 + lq + (qq & 1) * 8;
                int ci = wc * 4 + p * 2 + (qq >> 1);
                uint32_t t4[4];
                ldsm_x4_t(t4, sbase + OFF_Bb + sw_off(r, ci));
                bf[2 * p][0] = t4[0]; bf[2 * p][1] = t4[1];
                bf[2 * p + 1][0] = t4[2]; bf[2 * p + 1][1] = t4[3];
            }
#pragma unroll
            for (int mr = 0; mr < 3; mr++)
#pragma unroll
                for (int nt = 0; nt < 4; nt++)
                    mma_f16(acc[mr][nt], a[mr], bf[nt]);
        }

        // epilogue
        if (m == 0) {
            __syncthreads();      // all mma reads of A (X_query) done before overwrite
#pragma unroll
            for (int mr = 0; mr < 3; mr++) {
#pragma unroll
                for (int half = 0; half < 2; half++) {
                    int row = wr * 48 + mr * 16 + half * 8 + grp;
#pragma unroll
                    for (int nt = 0; nt < 4; nt++) {
                        int col = wc * 32 + nt * 8 + tid4 * 2;
                        __half2 hv = __float22half2_rn(make_float2(
                            fmaxf(acc[mr][nt][half * 2 + 0], 0.f),
                            fmaxf(acc[mr][nt][half * 2 + 1], 0.f)));
                        *(uint32_t*)(smb + sw_off(row, col >> 3) + (col & 7) * 2) = *(uint32_t*)&hv;
                    }
                }
            }
        } else {
#pragma unroll
            for (int mr = 0; mr < 3; mr++) {
#pragma unroll
                for (int half = 0; half < 2; half++) {
                    int row = wr * 48 + mr * 16 + half * 8 + grp;
                    int g = row / TT, t = row - g * TT;
                    char* dst = smb + KV_OFF(m - 1, g, t);
#pragma unroll
                    for (int nt = 0; nt < 4; nt++) {
                        int col = wc * 32 + nt * 8 + tid4 * 2;
                        __half2 hv = __float22half2_rn(make_float2(
                            fmaxf(acc[mr][nt][half * 2 + 0], 0.f),
                            fmaxf(acc[mr][nt][half * 2 + 1], 0.f)));
                        *(uint32_t*)(dst + col * 2) = *(uint32_t*)&hv;
                    }
                }
            }
        }
    }
    __syncthreads();      // q image + K,V complete

    // W image async copy into B region (overlaps attention)
    {
        const char* ws = (const char*)g_Wimg;
#pragma unroll
        for (int i = 0; i < 4; i++) {
            int c = i * 256 + tid;
            CP_ASYNC16(sbase + OFF_Bb + c * 16, ws + c * 16);
        }
        CP_COMMIT();
    }

    // ===== attention: warp = head, 4 reps over batches, sync-free =====
    const int h = wid;                // 8 warps = 8 heads
    const int t = lane;
#pragma unroll 1
    for (int gg = 0; gg < G4; gg++) {
        const long bn = (long)(b0 + gg) * NN + n;
        if (t < TT) {
            const int row = gg * TT + t;
            float qr[HD];
            {
                uint4 qa = *(const uint4*)(smb + sw_off(row, h * 2));
                uint4 qb = *(const uint4*)(smb + sw_off(row, h * 2 + 1));
                uint32_t qw[8] = {qa.x, qa.y, qa.z, qa.w, qb.x, qb.y, qb.z, qb.w};
#pragma unroll
                for (int e2 = 0; e2 < 8; e2++) {
                    float2 f = __half22float2(*(const __half2*)&qw[e2]);
                    qr[2 * e2] = f.x; qr[2 * e2 + 1] = f.y;
                }
            }
            float sc[TT];
#pragma unroll
            for (int s = 0; s < TT; s++) {
                const uint32_t* kp = (const uint32_t*)(smb + KV_OFF(0, gg, s) + h * 32);
                float a = 0.f;
#pragma unroll
                for (int e2 = 0; e2 < 8; e2++) {
                    uint32_t u = kp[e2];
                    float2 f = __half22float2(*(const __half2*)&u);
                    a += qr[2 * e2] * f.x + qr[2 * e2 + 1] * f.y;
                }
                sc[s] = a;
            }
            const float scale = 0.25f;
            float mx = -1e30f;
#pragma unroll
            for (int s = 0; s < TT; s++) if (s <= t) mx = fmaxf(mx, sc[s] * scale);
            float sum = 0.f;
#pragma unroll
            for (int s = 0; s < TT; s++) {
                float p = (s <= t) ? __expf(sc[s] * scale - mx) : 0.f;
                sc[s] = p; sum += p;
            }
            float inv = 1.f / sum;
#pragma unroll
            for (int s = 0; s < TT; s++) sc[s] *= inv;

            float o[HD];
#pragma unroll
            for (int d = 0; d < HD; d++) o[d] = 0.f;
#pragma unroll
            for (int s = 0; s < TT; s++) {
                const uint32_t* vp = (const uint32_t*)(smb + KV_OFF(1, gg, s) + h * 32);
                float pv = sc[s];
#pragma unroll
                for (int d2 = 0; d2 < 8; d2++) {
                    uint32_t u = vp[d2];
                    float2 f = __half22float2(*(const __half2*)&u);
                    o[2 * d2] += pv * f.x; o[2 * d2 + 1] += pv * f.y;
                }
            }
            // sO as fp16 into A image (overwrites this thread's q cols)
            {
                uint4 pk0, pk1;
                __half2 v0 = __float22half2_rn(make_float2(o[0], o[1]));
                __half2 v1 = __float22half2_rn(make_float2(o[2], o[3]));
                __half2 v2 = __float22half2_rn(make_float2(o[4], o[5]));
                __half2 v3 = __float22half2_rn(make_float2(o[6], o[7]));
                __half2 v4 = __float22half2_rn(make_float2(o[8], o[9]));
                __half2 v5 = __float22half2_rn(make_float2(o[10], o[11]));
                __half2 v6 = __float22half2_rn(make_float2(o[12], o[13]));
                __half2 v7 = __float22half2_rn(make_float2(o[14], o[15]));
                pk0.x = *(uint32_t*)&v0; pk0.y = *(uint32_t*)&v1;
                pk0.z = *(uint32_t*)&v2; pk0.w = *(uint32_t*)&v3;
                pk1.x = *(uint32_t*)&v4; pk1.y = *(uint32_t*)&v5;
                pk1.z = *(uint32_t*)&v6; pk1.w = *(uint32_t*)&v7;
                *(uint4*)(smb + sw_off(row, h * 2))     = pk0;
                *(uint4*)(smb + sw_off(row, h * 2 + 1)) = pk1;
            }
            if (write_attn) {
                float* ab = attn_out + (((bn * HH) + h) * TT + t) * TT;
#pragma unroll
                for (int s4 = 0; s4 < TT / 4; s4++)
                    ((float4*)ab)[s4] = make_float4(sc[4 * s4], sc[4 * s4 + 1], sc[4 * s4 + 2], sc[4 * s4 + 3]);
            }
        }
    }
    CP_WAIT0();
    __syncthreads();      // sO image complete, W image ready

    // ===== output projection: (96x128) @ (128x64) mma, bias+relu =====
    {
        float acc[3][2][4];
#pragma unroll
        for (int mr = 0; mr < 3; mr++)
#pragma unroll
            for (int nt = 0; nt < 2; nt++)
#pragma unroll
                for (int i = 0; i < 4; i++) acc[mr][nt][i] = 0.f;

#pragma unroll
        for (int kc = 0; kc < 8; kc++) {
            uint32_t a[3][4];
#pragma unroll
            for (int mr = 0; mr < 3; mr++) {
                int r = wr * 48 + mr * 16 + lq + (qq & 1) * 8;
                int ci = kc * 2 + (qq >> 1);
                ldsm_x4(a[mr], sbase + sw_off(r, ci));
            }
            uint32_t bf[2][2];
            {
                int r = kc * 16 + lq + (qq & 1) * 8;
                int ci = wc * 2 + (qq >> 1);
                uint32_t t4[4];
                ldsm_x4_t(t4, sbase + OFF_Bb + sw_off64(r, ci));
                bf[0][0] = t4[0]; bf[0][1] = t4[1];
                bf[1][0] = t4[2]; bf[1][1] = t4[3];
            }
#pragma unroll
            for (int mr = 0; mr < 3; mr++)
#pragma unroll
                for (int nt = 0; nt < 2; nt++)
                    mma_f16(acc[mr][nt], a[mr], bf[nt]);
        }

        float2 bias[2];
#pragma unroll
        for (int nt = 0; nt < 2; nt++) {
            int col = wc * 16 + nt * 8 + tid4 * 2;
            bias[nt] = make_float2(__ldg(outb + col), __ldg(outb + col + 1));
        }
#pragma unroll
        for (int mr = 0; mr < 3; mr++) {
#pragma unroll
            for (int half = 0; half < 2; half++) {
                int row = wr * 48 + mr * 16 + half * 8 + grp;
                int g = row / TT, t2 = row - g * TT;
                const long bn = (long)(b0 + g) * NN + n;
                float* op = out + ((bn * TT) + t2) * DMOUT;
#pragma unroll
                for (int nt = 0; nt < 2; nt++) {
                    int col = wc * 16 + nt * 8 + tid4 * 2;
                    *(float2*)(op + col) = make_float2(
                        fmaxf(acc[mr][nt][half * 2 + 0] + bias[nt].x, 0.f),
                        fmaxf(acc[mr][nt][half * 2 + 1] + bias[nt].y, 0.f));
                }
            }
        }
    }
}

// ---------------- launch ----------------
extern "C" void kernel_launch(void* const* d_in, const int* in_sizes, int n_in,
                              void* d_out, int out_size) {
    const float* query = (const float*)d_in[0];
    const float* key_  = (const float*)d_in[1];
    const float* value = (const float*)d_in[2];
    const float* qp1 = (const float*)d_in[4];
    const float* qp2 = (const float*)d_in[5];
    const float* kp1 = (const float*)d_in[6];
    const float* kp2 = (const float*)d_in[7];
    const float* vp1 = (const float*)d_in[8];
    const float* vp2 = (const float*)d_in[9];
    const float* outW = (const float*)d_in[10];
    const float* outb = (const float*)d_in[11];

    float* out = (float*)d_out;
    int write_attn = (out_size >= OUT_N + ATTN_N) ? 1 : 0;

    static int attr_done = 0;
    if (!attr_done) {
        cudaFuncSetAttribute(prep_P_kernel, cudaFuncAttributeMaxDynamicSharedMemorySize, PP_SMEM);
        cudaFuncSetAttribute(fused_kernel, cudaFuncAttributeMaxDynamicSharedMemorySize, SMEMF_TOTAL);
        attr_done = 1;
    }

    prep_P_kernel<<<dim3(NN, 3), 256, PP_SMEM>>>(qp1, qp2, kp1, kp2, vp1, vp2);
    prep_W_kernel<<<1, 256>>>(outW);
    fused_kernel<<<dim3(NN, BB / G4), 256, SMEMF_TOTAL>>>(
        query, key_, value, outb, out, out + OUT_N, write_attn);
}

// round 13
// speedup vs baseline: 4.0008x; 1.6125x over previous
#include <cuda_runtime.h>
#include <cuda_fp16.h>
#include <cuda_bf16.h>
#include <cstdint>

// ---------------- problem constants ----------------
#define BB 32
#define NN 207
#define TT 24
#define EE 128
#define HH 8
#define HD 16
#define DMOUT 64
#define MM 32
#define G4 4                         // batches per fused block

#define OUT_N (BB * NN * TT * DMOUT)
#define ATTN_N (BB * NN * HH * TT * TT)

// P images: per (m,n): 128 k-rows x 128 n-cols fp16, swizzled (32KB)
__device__ __align__(16) __half g_Pimg[(size_t)3 * NN * 16384];
// W image: 128 k-rows x 64 n-cols fp16, 128B-row swizzle (16KB)
__device__ __align__(16) __half g_Wimg[8192];

// ---------------- helpers ----------------
__device__ __forceinline__ uint32_t smem_u32(const void* p) {
    uint32_t a;
    asm("{ .reg .u64 t; cvta.to.shared.u64 t, %1; cvt.u32.u64 %0, t; }" : "=r"(a) : "l"(p));
    return a;
}
// swizzled byte offset: 256B rows, 16B chunks ci 0..15
__device__ __forceinline__ uint32_t sw_off(int r, int ci) {
    return (uint32_t)r * 256u + (uint32_t)((ci ^ (r & 7)) << 4);
}
// swizzled byte offset: 128B rows, 16B chunks ci 0..7
__device__ __forceinline__ uint32_t sw_off64(int r, int ci) {
    return (uint32_t)r * 128u + (uint32_t)((ci ^ (r & 7)) << 4);
}
__device__ __forceinline__ void ldsm_x4(uint32_t* r, uint32_t addr) {
    asm volatile("ldmatrix.sync.aligned.m8n8.x4.shared.b16 {%0,%1,%2,%3}, [%4];"
                 : "=r"(r[0]), "=r"(r[1]), "=r"(r[2]), "=r"(r[3]) : "r"(addr));
}
__device__ __forceinline__ void ldsm_x4_t(uint32_t* r, uint32_t addr) {
    asm volatile("ldmatrix.sync.aligned.m8n8.x4.trans.shared.b16 {%0,%1,%2,%3}, [%4];"
                 : "=r"(r[0]), "=r"(r[1]), "=r"(r[2]), "=r"(r[3]) : "r"(addr));
}
__device__ __forceinline__ void mma_f16(float* d, const uint32_t* a, const uint32_t* b) {
    asm volatile("mma.sync.aligned.m16n8k16.row.col.f32.f16.f16.f32 "
                 "{%0,%1,%2,%3}, {%4,%5,%6,%7}, {%8,%9}, {%0,%1,%2,%3};"
                 : "+f"(d[0]), "+f"(d[1]), "+f"(d[2]), "+f"(d[3])
                 : "r"(a[0]), "r"(a[1]), "r"(a[2]), "r"(a[3]), "r"(b[0]), "r"(b[1]));
}
__device__ __forceinline__ void mma_bf16(float* d, const uint32_t* a, const uint32_t* b) {
    asm volatile("mma.sync.aligned.m16n8k16.row.col.f32.bf16.bf16.f32 "
                 "{%0,%1,%2,%3}, {%4,%5,%6,%7}, {%8,%9}, {%0,%1,%2,%3};"
                 : "+f"(d[0]), "+f"(d[1]), "+f"(d[2]), "+f"(d[3])
                 : "r"(a[0]), "r"(a[1]), "r"(a[2]), "r"(a[3]), "r"(b[0]), "r"(b[1]));
}
#define CP_ASYNC16(dst, src) \
    asm volatile("cp.async.cg.shared.global [%0], [%1], 16;" :: "r"(dst), "l"(src))
#define CP_COMMIT() asm volatile("cp.async.commit_group;")
#define CP_WAIT0()  asm volatile("cp.async.wait_group 0;")

__device__ __forceinline__ uint32_t pack_bf16(float x, float y) {
    __nv_bfloat16 h0 = __float2bfloat16(x);
    __nv_bfloat16 h1 = __float2bfloat16(y);
    return (uint32_t)__bfloat16_as_ushort(h0) | ((uint32_t)__bfloat16_as_ushort(h1) << 16);
}
__device__ __forceinline__ uint32_t pack_h2(float x, float y) {
    __half2 h = __float22half2_rn(make_float2(x, y));
    return *(uint32_t*)&h;
}

// ---------------- kernel 0: P images via tensor cores (bf16 3-pass split) ----------------
#define PP_AL   16384
#define PP_B    32768
#define PP_IMG  65536
#define PP_SMEM 98304

__global__ __launch_bounds__(256, 2) void prep_P_kernel(
    const float* __restrict__ qp1, const float* __restrict__ qp2,
    const float* __restrict__ kp1, const float* __restrict__ kp2,
    const float* __restrict__ vp1, const float* __restrict__ vp2) {
    extern __shared__ float sm0[];
    char* smb = (char*)sm0;
    const uint32_t sbase = smem_u32(smb);

    const int n = blockIdx.x, m = blockIdx.y, tid = threadIdx.x;
    const int wid = tid >> 5, lane = tid & 31;
    const int wr = wid >> 2, wc = wid & 3;       // warp grid 2(M) x 4(N)
    const int grp = lane >> 2, tid4 = lane & 3;
    const int lq = lane & 7, qq = lane >> 3;

    const float* p1 = (m == 0) ? qp1 : ((m == 1) ? kp1 : vp1);
    const float* p2 = (m == 0) ? qp2 : ((m == 1) ? kp2 : vp2);

    {
        const float* p1b = p1 + (size_t)n * 2048;
#pragma unroll
        for (int it = 0; it < 4; it++) {
            int idx2 = it * 256 + tid;
            int r = idx2 >> 4, cp = idx2 & 15;
            float2 v = *(const float2*)(p1b + r * 32 + 2 * cp);
            float hx = __bfloat162float(__float2bfloat16(v.x));
            float hy = __bfloat162float(__float2bfloat16(v.y));
            uint32_t off = sw_off(r, cp >> 2) + (uint32_t)(cp & 3) * 4u;
            *(uint32_t*)(smb + off)         = pack_bf16(v.x, v.y);
            *(uint32_t*)(smb + PP_AL + off) = pack_bf16(v.x - hx, v.y - hy);
        }
    }
    {
#pragma unroll
        for (int it = 0; it < 16; it++) {
            int idx2 = it * 256 + tid;
            int r = idx2 >> 7, cp = idx2 & 127;
            float2 v = *(const float2*)(p2 + r * 256 + 2 * cp);
            int jj = cp >> 6, lcp = cp & 63;
            float hx = __bfloat162float(__float2bfloat16(v.x));
            float hy = __bfloat162float(__float2bfloat16(v.y));
            uint32_t off = sw_off(r, lcp >> 2) + (uint32_t)(lcp & 3) * 4u;
            char* bb = smb + PP_B + jj * 16384;
            *(uint32_t*)(bb + off)        = pack_bf16(v.x, v.y);
            *(uint32_t*)(bb + 8192 + off) = pack_bf16(v.x - hx, v.y - hy);
        }
    }
    __syncthreads();

#pragma unroll
    for (int j = 0; j < 2; j++) {
        float acc[2][4][4];
#pragma unroll
        for (int mr = 0; mr < 2; mr++)
#pragma unroll
            for (int nt = 0; nt < 4; nt++)
#pragma unroll
                for (int i = 0; i < 4; i++) acc[mr][nt][i] = 0.f;

        const uint32_t Ao[3] = {0u, PP_AL, 0u};
        const uint32_t Bo[3] = {0u, 0u, 8192u};
#pragma unroll
        for (int pass = 0; pass < 3; pass++) {
            const uint32_t aB = sbase + Ao[pass];
            const uint32_t bB = sbase + PP_B + (uint32_t)j * 16384u + Bo[pass];
#pragma unroll
            for (int kc = 0; kc < 2; kc++) {
                uint32_t a[2][4];
#pragma unroll
                for (int mr = 0; mr < 2; mr++) {
                    int r = wr * 32 + mr * 16 + lq + (qq & 1) * 8;
                    int ci = kc * 2 + (qq >> 1);
                    ldsm_x4(a[mr], aB + sw_off(r, ci));
                }
                uint32_t bf[4][2];
#pragma unroll
                for (int p = 0; p < 2; p++) {
                    int r = kc * 16 + lq + (qq & 1) * 8;
                    int ci = wc * 4 + p * 2 + (qq >> 1);
                    uint32_t t4r[4];
                    ldsm_x4_t(t4r, bB + sw_off(r, ci));
                    bf[2 * p][0] = t4r[0]; bf[2 * p][1] = t4r[1];
                    bf[2 * p + 1][0] = t4r[2]; bf[2 * p + 1][1] = t4r[3];
                }
#pragma unroll
                for (int mr = 0; mr < 2; mr++)
#pragma unroll
                    for (int nt = 0; nt < 4; nt++)
                        mma_bf16(acc[mr][nt], a[mr], bf[nt]);
            }
        }
#pragma unroll
        for (int mr = 0; mr < 2; mr++) {
#pragma unroll
            for (int half = 0; half < 2; half++) {
                int i_row = wr * 32 + mr * 16 + half * 8 + grp;
                int k = 2 * i_row + j;
#pragma unroll
                for (int nt = 0; nt < 4; nt++) {
                    int c = wc * 32 + nt * 8 + tid4 * 2;
                    *(uint32_t*)(smb + PP_IMG + sw_off(k, c >> 3) + tid4 * 4) =
                        pack_h2(acc[mr][nt][half * 2 + 0], acc[mr][nt][half * 2 + 1]);
                }
            }
        }
    }
    __syncthreads();

    float4* dst = (float4*)(g_Pimg + (size_t)(m * NN + n) * 16384);
    const float4* src = (const float4*)(smb + PP_IMG);
#pragma unroll
    for (int i = 0; i < 8; i++)
        dst[i * 256 + tid] = src[i * 256 + tid];
}

// ---------------- kernel 0b: W image (fp16, 128B-row swizzle) ----------------
__global__ void prep_W_kernel(const float* __restrict__ outW) {
    int tid = threadIdx.x;
    char* gbase = (char*)g_Wimg;
#pragma unroll
    for (int it = 0; it < 16; it++) {
        int idx = it * 256 + tid;
        int k = idx >> 5, n2 = idx & 31;
        float2 v = *(const float2*)(outW + k * DMOUT + 2 * n2);
        uint32_t off = sw_off64(k, n2 >> 2) + (uint32_t)(n2 & 3) * 4u;
        *(uint32_t*)(gbase + off) = pack_h2(v.x, v.y);
    }
}

// ---------------- fused kernel: 4 batches per block, 2 CTAs/SM, tensor attention ----------------
// smem bytes per CTA (106,496):
//  [A 0..24576)      96x128 fp16 swizzled (X during proj; Q image -> sO after)
//  [B 24576..57344)  P image during proj; W image (16KB) after
//  [K 57344..81920)  96x128 fp16 swizzled K image
//  [V 81920..106496) 96x128 fp16 swizzled V image
#define OFF_Bb 24576
#define OFF_K  57344
#define OFF_V  81920
#define SMEMF_TOTAL 106496

__global__ __launch_bounds__(256, 2) void fused_kernel(
    const float* __restrict__ query, const float* __restrict__ key_,
    const float* __restrict__ value,
    const float* __restrict__ outb,
    float* __restrict__ out, float* __restrict__ attn_out, int write_attn) {
    extern __shared__ float smf[];
    char* smb = (char*)smf;
    const uint32_t sbase = smem_u32(smb);

    const int n = blockIdx.x;
    const int b0 = blockIdx.y * G4;
    const int tid = threadIdx.x, wid = tid >> 5, lane = tid & 31;
    const int wr = wid >> 2, wc = wid & 3;        // warp grid 2(M) x 4(N)
    const int grp = lane >> 2, tid4 = lane & 3;
    const int lq = lane & 7, qq = lane >> 3;

    // ===== three projections (M=96 = 4 batches x 24), order k, v, q =====
    for (int mi = 0; mi < 3; mi++) {
        const int m = (mi + 1) % 3;               // 1, 2, 0
        if (mi) __syncthreads();
        {
            const char* bs = (const char*)(g_Pimg + (size_t)(m * NN + n) * 16384);
            uint32_t bd = sbase + OFF_Bb;
#pragma unroll
            for (int i = 0; i < 8; i++) {
                int c = i * 256 + tid;
                CP_ASYNC16(bd + c * 16, bs + c * 16);
            }
            CP_COMMIT();
        }
        {
            const float* x = (m == 0) ? query : ((m == 1) ? key_ : value);
#pragma unroll
            for (int it = 0; it < 12; it++) {
                int idx = it * 256 + tid;          // 3072 float4 jobs
                int r = idx >> 5, c4 = idx & 31;
                int g = r / TT, t = r - g * TT;
                float4 v = *(const float4*)(x + (((size_t)(b0 + g) * NN + n) * TT + t) * EE + 4 * c4);
                uint2 pk;
                pk.x = pack_h2(v.x, v.y);
                pk.y = pack_h2(v.z, v.w);
                uint32_t off = sw_off(r, c4 >> 1) + (uint32_t)(c4 & 1) * 8u;
                *(uint2*)(smb + off) = pk;
            }
        }
        CP_WAIT0();
        __syncthreads();

        // GEMM 96 x 128 x 128, single pass fp16
        float acc[3][4][4];
#pragma unroll
        for (int mr = 0; mr < 3; mr++)
#pragma unroll
            for (int nt = 0; nt < 4; nt++)
#pragma unroll
                for (int i = 0; i < 4; i++) acc[mr][nt][i] = 0.f;

#pragma unroll
        for (int kc = 0; kc < 8; kc++) {
            uint32_t a[3][4];
#pragma unroll
            for (int mr = 0; mr < 3; mr++) {
                int r = wr * 48 + mr * 16 + lq + (qq & 1) * 8;
                int ci = kc * 2 + (qq >> 1);
                ldsm_x4(a[mr], sbase + sw_off(r, ci));
            }
            uint32_t bf[4][2];
#pragma unroll
            for (int p = 0; p < 2; p++) {
                int r = kc * 16 + lq + (qq & 1) * 8;
                int ci = wc * 4 + p * 2 + (qq >> 1);
                uint32_t t4r[4];
                ldsm_x4_t(t4r, sbase + OFF_Bb + sw_off(r, ci));
                bf[2 * p][0] = t4r[0]; bf[2 * p][1] = t4r[1];
                bf[2 * p + 1][0] = t4r[2]; bf[2 * p + 1][1] = t4r[3];
            }
#pragma unroll
            for (int mr = 0; mr < 3; mr++)
#pragma unroll
                for (int nt = 0; nt < 4; nt++)
                    mma_f16(acc[mr][nt], a[mr], bf[nt]);
        }

        // epilogue: relu -> swizzled image (A for q, K/V images for k/v)
        const uint32_t obase = (m == 0) ? 0u : ((m == 1) ? (uint32_t)OFF_K : (uint32_t)OFF_V);
        if (m == 0) __syncthreads();   // all mma reads of A (X_query) done before overwrite
#pragma unroll
        for (int mr = 0; mr < 3; mr++) {
#pragma unroll
            for (int half = 0; half < 2; half++) {
                int row = wr * 48 + mr * 16 + half * 8 + grp;
#pragma unroll
                for (int nt = 0; nt < 4; nt++) {
                    int col = wc * 32 + nt * 8 + tid4 * 2;
                    *(uint32_t*)(smb + obase + sw_off(row, col >> 3) + (col & 7) * 2) =
                        pack_h2(fmaxf(acc[mr][nt][half * 2 + 0], 0.f),
                                fmaxf(acc[mr][nt][half * 2 + 1], 0.f));
                }
            }
        }
    }
    __syncthreads();      // Q image + K,V images complete

    // W image async copy into B region (overlaps attention)
    {
        const char* ws = (const char*)g_Wimg;
#pragma unroll
        for (int i = 0; i < 4; i++) {
            int c = i * 256 + tid;
            CP_ASYNC16(sbase + OFF_Bb + c * 16, ws + c * 16);
        }
        CP_COMMIT();
    }

    // ===== tensor-core attention: warp = head, loop over 4 batches, sync-free =====
    const int h = wid;                            // 8 warps = 8 heads
    const int ci_h = h * 2 + (qq >> 1);
#pragma unroll 1
    for (int g = 0; g < G4; g++) {
        const int rowb = g * TT;
        const long bn = (long)(b0 + g) * NN + n;

        // Q A-frags (2 m-tiles) and K B-frags (3 n-tiles of s)
        uint32_t aq[2][4], kf[2][4];
#pragma unroll
        for (int mt = 0; mt < 2; mt++) {
            int r = rowb + mt * 16 + lq + (qq & 1) * 8;
            if (r > 95) r = 95;
            ldsm_x4(aq[mt], sbase + sw_off(r, ci_h));
        }
#pragma unroll
        for (int st = 0; st < 2; st++) {
            int r = rowb + st * 16 + lq + (qq & 1) * 8;
            if (r > 95) r = 95;
            ldsm_x4(kf[st], sbase + OFF_K + sw_off(r, ci_h));
        }
        uint32_t bK[3][2];
        bK[0][0] = kf[0][0]; bK[0][1] = kf[0][2];
        bK[1][0] = kf[0][1]; bK[1][1] = kf[0][3];
        bK[2][0] = kf[1][0]; bK[2][1] = kf[1][2];

        float S[2][3][4];
#pragma unroll
        for (int mt = 0; mt < 2; mt++)
#pragma unroll
            for (int nt = 0; nt < 3; nt++) {
#pragma unroll
                for (int i = 0; i < 4; i++) S[mt][nt][i] = 0.f;
                mma_f16(S[mt][nt], aq[mt], bK[nt]);
            }

        // softmax over s (cols), causal mask, in fragments
#pragma unroll
        for (int mt = 0; mt < 2; mt++) {
#pragma unroll
            for (int rh = 0; rh < 2; rh++) {
                int tloc = mt * 16 + grp + rh * 8;
                float x[3][2];
                float mx = -1e30f;
#pragma unroll
                for (int nt = 0; nt < 3; nt++)
#pragma unroll
                    for (int c = 0; c < 2; c++) {
                        int s = nt * 8 + 2 * tid4 + c;
                        bool ok = (tloc < TT) && (s <= tloc);
                        float v = ok ? S[mt][nt][rh * 2 + c] * 0.25f : -1e30f;
                        x[nt][c] = v;
                        mx = fmaxf(mx, v);
                    }
                mx = fmaxf(mx, __shfl_xor_sync(0xffffffffu, mx, 1));
                mx = fmaxf(mx, __shfl_xor_sync(0xffffffffu, mx, 2));
                float sum = 0.f;
#pragma unroll
                for (int nt = 0; nt < 3; nt++)
#pragma unroll
                    for (int c = 0; c < 2; c++) {
                        float e = (x[nt][c] > -1e29f) ? __expf(x[nt][c] - mx) : 0.f;
                        x[nt][c] = e;
                        sum += e;
                    }
                sum += __shfl_xor_sync(0xffffffffu, sum, 1);
                sum += __shfl_xor_sync(0xffffffffu, sum, 2);
                float inv = (sum > 0.f) ? (1.f / sum) : 0.f;
#pragma unroll
                for (int nt = 0; nt < 3; nt++)
#pragma unroll
                    for (int c = 0; c < 2; c++)
                        S[mt][nt][rh * 2 + c] = x[nt][c] * inv;
            }
        }

        // write attn probabilities (fp32, valid rows only)
        if (write_attn) {
            const float* Sv;
#pragma unroll
            for (int vr = 0; vr < 3; vr++) {      // (mt,rh) in {(0,0),(0,1),(1,0)}
                int mt = (vr == 2) ? 1 : 0;
                int rh = (vr == 1) ? 1 : 0;
                int tloc = mt * 16 + grp + rh * 8;
                float* ab = attn_out + (((bn * HH) + h) * TT + tloc) * TT + 2 * tid4;
#pragma unroll
                for (int nt = 0; nt < 3; nt++)
                    *(float2*)(ab + nt * 8) =
                        make_float2(S[mt][nt][rh * 2 + 0], S[mt][nt][rh * 2 + 1]);
            }
            (void)Sv;
        }

        // pack P to fp16 A-frags: [mt][kchunk][4]
        uint32_t pa[2][2][4];
#pragma unroll
        for (int mt = 0; mt < 2; mt++) {
            pa[mt][0][0] = pack_h2(S[mt][0][0], S[mt][0][1]);
            pa[mt][0][1] = pack_h2(S[mt][0][2], S[mt][0][3]);
            pa[mt][0][2] = pack_h2(S[mt][1][0], S[mt][1][1]);
            pa[mt][0][3] = pack_h2(S[mt][1][2], S[mt][1][3]);
            pa[mt][1][0] = pack_h2(S[mt][2][0], S[mt][2][1]);
            pa[mt][1][1] = pack_h2(S[mt][2][2], S[mt][2][3]);
            pa[mt][1][2] = 0u;
            pa[mt][1][3] = 0u;
        }

        // V B-frags (2 k-chunks x 2 d-tiles)
        uint32_t vf[2][4];
#pragma unroll
        for (int kc = 0; kc < 2; kc++) {
            int r = rowb + kc * 16 + lq + (qq & 1) * 8;
            if (r > 95) r = 95;
            ldsm_x4_t(vf[kc], sbase + OFF_V + sw_off(r, ci_h));
        }

        float O[2][2][4];
#pragma unroll
        for (int mt = 0; mt < 2; mt++)
#pragma unroll
            for (int ntd = 0; ntd < 2; ntd++) {
#pragma unroll
                for (int i = 0; i < 4; i++) O[mt][ntd][i] = 0.f;
#pragma unroll
                for (int kc = 0; kc < 2; kc++) {
                    uint32_t bv[2] = {vf[kc][ntd * 2], vf[kc][ntd * 2 + 1]};
                    mma_f16(O[mt][ntd], pa[mt][kc], bv);
                }
            }

        // sO as fp16 into A image (same cols this warp read Q from)
#pragma unroll
        for (int mt = 0; mt < 2; mt++) {
#pragma unroll
            for (int ntd = 0; ntd < 2; ntd++) {
                int row0 = rowb + mt * 16 + grp;
                int col = h * 16 + ntd * 8 + 2 * tid4;
                *(uint32_t*)(smb + sw_off(row0, col >> 3) + (col & 7) * 2) =
                    pack_h2(O[mt][ntd][0], O[mt][ntd][1]);
                if (mt == 0)
                    *(uint32_t*)(smb + sw_off(row0 + 8, col >> 3) + (col & 7) * 2) =
                        pack_h2(O[mt][ntd][2], O[mt][ntd][3]);
            }
        }
    }
    CP_WAIT0();
    __syncthreads();      // sO image complete, W image ready

    // ===== output projection: (96x128) @ (128x64) mma, bias+relu =====
    {
        float acc[3][2][4];
#pragma unroll
        for (int mr = 0; mr < 3; mr++)
#pragma unroll
            for (int nt = 0; nt < 2; nt++)
#pragma unroll
                for (int i = 0; i < 4; i++) acc[mr][nt][i] = 0.f;

#pragma unroll
        for (int kc = 0; kc < 8; kc++) {
            uint32_t a[3][4];
#pragma unroll
            for (int mr = 0; mr < 3; mr++) {
                int r = wr * 48 + mr * 16 + lq + (qq & 1) * 8;
                int ci = kc * 2 + (qq >> 1);
                ldsm_x4(a[mr], sbase + sw_off(r, ci));
            }
            uint32_t bf[2][2];
            {
                int r = kc * 16 + lq + (qq & 1) * 8;
                int ci = wc * 2 + (qq >> 1);
                uint32_t t4r[4];
                ldsm_x4_t(t4r, sbase + OFF_Bb + sw_off64(r, ci));
                bf[0][0] = t4r[0]; bf[0][1] = t4r[1];
                bf[1][0] = t4r[2]; bf[1][1] = t4r[3];
            }
#pragma unroll
            for (int mr = 0; mr < 3; mr++)
#pragma unroll
                for (int nt = 0; nt < 2; nt++)
                    mma_f16(acc[mr][nt], a[mr], bf[nt]);
        }

        float2 bias[2];
#pragma unroll
        for (int nt = 0; nt < 2; nt++) {
            int col = wc * 16 + nt * 8 + tid4 * 2;
            bias[nt] = make_float2(__ldg(outb + col), __ldg(outb + col + 1));
        }
#pragma unroll
        for (int mr = 0; mr < 3; mr++) {
#pragma unroll
            for (int half = 0; half < 2; half++) {
                int row = wr * 48 + mr * 16 + half * 8 + grp;
                int g = row / TT, t2 = row - g * TT;
                const long bn = (long)(b0 + g) * NN + n;
                float* op = out + ((bn * TT) + t2) * DMOUT;
#pragma unroll
                for (int nt = 0; nt < 2; nt++) {
                    int col = wc * 16 + nt * 8 + tid4 * 2;
                    *(float2*)(op + col) = make_float2(
                        fmaxf(acc[mr][nt][half * 2 + 0] + bias[nt].x, 0.f),
                        fmaxf(acc[mr][nt][half * 2 + 1] + bias[nt].y, 0.f));
                }
            }
        }
    }
}

// ---------------- launch ----------------
extern "C" void kernel_launch(void* const* d_in, const int* in_sizes, int n_in,
                              void* d_out, int out_size) {
    const float* query = (const float*)d_in[0];
    const float* key_  = (const float*)d_in[1];
    const float* value = (const float*)d_in[2];
    const float* qp1 = (const float*)d_in[4];
    const float* qp2 = (const float*)d_in[5];
    const float* kp1 = (const float*)d_in[6];
    const float* kp2 = (const float*)d_in[7];
    const float* vp1 = (const float*)d_in[8];
    const float* vp2 = (const float*)d_in[9];
    const float* outW = (const float*)d_in[10];
    const float* outb = (const float*)d_in[11];

    float* out = (float*)d_out;
    int write_attn = (out_size >= OUT_N + ATTN_N) ? 1 : 0;

    static int attr_done = 0;
    if (!attr_done) {
        cudaFuncSetAttribute(prep_P_kernel, cudaFuncAttributeMaxDynamicSharedMemorySize, PP_SMEM);
        cudaFuncSetAttribute(fused_kernel, cudaFuncAttributeMaxDynamicSharedMemorySize, SMEMF_TOTAL);
        attr_done = 1;
    }

    prep_P_kernel<<<dim3(NN, 3), 256, PP_SMEM>>>(qp1, qp2, kp1, kp2, vp1, vp2);
    prep_W_kernel<<<1, 256>>>(outW);
    fused_kernel<<<dim3(NN, BB / G4), 256, SMEMF_TOTAL>>>(
        query, key_, value, outb, out, out + OUT_N, write_attn);
}

// round 14
// speedup vs baseline: 4.0016x; 1.0002x over previous
#include <cuda_runtime.h>
#include <cuda_fp16.h>
#include <cuda_bf16.h>
#include <cstdint>

// ---------------- problem constants ----------------
#define BB 32
#define NN 207
#define TT 24
#define EE 128
#define HH 8
#define HD 16
#define DMOUT 64
#define MM 32
#define G4 4                         // batches per fused block

#define OUT_N (BB * NN * TT * DMOUT)
#define ATTN_N (BB * NN * HH * TT * TT)

// P images: per (m,n): 128 k-rows x 128 n-cols fp16, swizzled (32KB)
__device__ __align__(16) __half g_Pimg[(size_t)3 * NN * 16384];
// W image: 128 k-rows x 64 n-cols fp16, 128B-row swizzle (16KB)
__device__ __align__(16) __half g_Wimg[8192];

// ---------------- helpers ----------------
__device__ __forceinline__ uint32_t smem_u32(const void* p) {
    uint32_t a;
    asm("{ .reg .u64 t; cvta.to.shared.u64 t, %1; cvt.u32.u64 %0, t; }" : "=r"(a) : "l"(p));
    return a;
}
// swizzled byte offset: 256B rows, 16B chunks ci 0..15
__device__ __forceinline__ uint32_t sw_off(int r, int ci) {
    return (uint32_t)r * 256u + (uint32_t)((ci ^ (r & 7)) << 4);
}
// swizzled byte offset: 128B rows, 16B chunks ci 0..7
__device__ __forceinline__ uint32_t sw_off64(int r, int ci) {
    return (uint32_t)r * 128u + (uint32_t)((ci ^ (r & 7)) << 4);
}
__device__ __forceinline__ void ldsm_x4(uint32_t* r, uint32_t addr) {
    asm volatile("ldmatrix.sync.aligned.m8n8.x4.shared.b16 {%0,%1,%2,%3}, [%4];"
                 : "=r"(r[0]), "=r"(r[1]), "=r"(r[2]), "=r"(r[3]) : "r"(addr));
}
__device__ __forceinline__ void ldsm_x4_t(uint32_t* r, uint32_t addr) {
    asm volatile("ldmatrix.sync.aligned.m8n8.x4.trans.shared.b16 {%0,%1,%2,%3}, [%4];"
                 : "=r"(r[0]), "=r"(r[1]), "=r"(r[2]), "=r"(r[3]) : "r"(addr));
}
__device__ __forceinline__ void mma_f16(float* d, const uint32_t* a, const uint32_t* b) {
    asm volatile("mma.sync.aligned.m16n8k16.row.col.f32.f16.f16.f32 "
                 "{%0,%1,%2,%3}, {%4,%5,%6,%7}, {%8,%9}, {%0,%1,%2,%3};"
                 : "+f"(d[0]), "+f"(d[1]), "+f"(d[2]), "+f"(d[3])
                 : "r"(a[0]), "r"(a[1]), "r"(a[2]), "r"(a[3]), "r"(b[0]), "r"(b[1]));
}
__device__ __forceinline__ void mma_bf16(float* d, const uint32_t* a, const uint32_t* b) {
    asm volatile("mma.sync.aligned.m16n8k16.row.col.f32.bf16.bf16.f32 "
                 "{%0,%1,%2,%3}, {%4,%5,%6,%7}, {%8,%9}, {%0,%1,%2,%3};"
                 : "+f"(d[0]), "+f"(d[1]), "+f"(d[2]), "+f"(d[3])
                 : "r"(a[0]), "r"(a[1]), "r"(a[2]), "r"(a[3]), "r"(b[0]), "r"(b[1]));
}
#define CP_ASYNC16(dst, src) \
    asm volatile("cp.async.cg.shared.global [%0], [%1], 16;" :: "r"(dst), "l"(src))
#define CP_COMMIT() asm volatile("cp.async.commit_group;")
#define CP_WAIT0()  asm volatile("cp.async.wait_group 0;")

__device__ __forceinline__ uint32_t pack_bf16(float x, float y) {
    __nv_bfloat16 h0 = __float2bfloat16(x);
    __nv_bfloat16 h1 = __float2bfloat16(y);
    return (uint32_t)__bfloat16_as_ushort(h0) | ((uint32_t)__bfloat16_as_ushort(h1) << 16);
}
__device__ __forceinline__ uint32_t pack_h2(float x, float y) {
    __half2 h = __float22half2_rn(make_float2(x, y));
    return *(uint32_t*)&h;
}

// ---------------- kernel 0: P images (all 3 matrices per block) + W image ----------------
#define PP_AL   16384
#define PP_B    32768
#define PP_IMG  65536
#define PP_SMEM 98304

__global__ __launch_bounds__(256, 2) void prep_P_kernel(
    const float* __restrict__ qp1, const float* __restrict__ qp2,
    const float* __restrict__ kp1, const float* __restrict__ kp2,
    const float* __restrict__ vp1, const float* __restrict__ vp2,
    const float* __restrict__ outW) {
    extern __shared__ float sm0[];
    char* smb = (char*)sm0;
    const uint32_t sbase = smem_u32(smb);

    const int n = blockIdx.x, tid = threadIdx.x;
    const int wid = tid >> 5, lane = tid & 31;
    const int wr = wid >> 2, wc = wid & 3;       // warp grid 2(M) x 4(N)
    const int grp = lane >> 2, tid4 = lane & 3;
    const int lq = lane & 7, qq = lane >> 3;

    // block 0 also builds the W image (gmem only, no smem)
    if (n == 0) {
        char* gbase = (char*)g_Wimg;
#pragma unroll
        for (int it = 0; it < 16; it++) {
            int idx = it * 256 + tid;
            int k = idx >> 5, n2 = idx & 31;
            float2 v = *(const float2*)(outW + k * DMOUT + 2 * n2);
            uint32_t off = sw_off64(k, n2 >> 2) + (uint32_t)(n2 & 3) * 4u;
            *(uint32_t*)(gbase + off) = pack_h2(v.x, v.y);
        }
    }

    for (int m = 0; m < 3; m++) {
        if (m) __syncthreads();     // previous bulk-store reads of PP_IMG / GEMM reads done
        const float* p1 = (m == 0) ? qp1 : ((m == 1) ? kp1 : vp1);
        const float* p2 = (m == 0) ? qp2 : ((m == 1) ? kp2 : vp2);

        // stage p1 (64x32 fp32) -> Ah/Al bf16 swizzled
        {
            const float* p1b = p1 + (size_t)n * 2048;
#pragma unroll
            for (int it = 0; it < 4; it++) {
                int idx2 = it * 256 + tid;
                int r = idx2 >> 4, cp = idx2 & 15;
                float2 v = *(const float2*)(p1b + r * 32 + 2 * cp);
                float hx = __bfloat162float(__float2bfloat16(v.x));
                float hy = __bfloat162float(__float2bfloat16(v.y));
                uint32_t off = sw_off(r, cp >> 2) + (uint32_t)(cp & 3) * 4u;
                *(uint32_t*)(smb + off)         = pack_bf16(v.x, v.y);
                *(uint32_t*)(smb + PP_AL + off) = pack_bf16(v.x - hx, v.y - hy);
            }
        }
        // stage p2 (32x256 fp32) -> B0h/B0l/B1h/B1l bf16 swizzled
        {
#pragma unroll
            for (int it = 0; it < 16; it++) {
                int idx2 = it * 256 + tid;
                int r = idx2 >> 7, cp = idx2 & 127;
                float2 v = *(const float2*)(p2 + r * 256 + 2 * cp);
                int jj = cp >> 6, lcp = cp & 63;
                float hx = __bfloat162float(__float2bfloat16(v.x));
                float hy = __bfloat162float(__float2bfloat16(v.y));
                uint32_t off = sw_off(r, lcp >> 2) + (uint32_t)(lcp & 3) * 4u;
                char* bb = smb + PP_B + jj * 16384;
                *(uint32_t*)(bb + off)        = pack_bf16(v.x, v.y);
                *(uint32_t*)(bb + 8192 + off) = pack_bf16(v.x - hx, v.y - hy);
            }
        }
        __syncthreads();

        // two GEMMs (j = 0,1): 64x128x32, bf16 3-pass split
#pragma unroll
        for (int j = 0; j < 2; j++) {
            float acc[2][4][4];
#pragma unroll
            for (int mr = 0; mr < 2; mr++)
#pragma unroll
                for (int nt = 0; nt < 4; nt++)
#pragma unroll
                    for (int i = 0; i < 4; i++) acc[mr][nt][i] = 0.f;

            const uint32_t Ao[3] = {0u, PP_AL, 0u};
            const uint32_t Bo[3] = {0u, 0u, 8192u};
#pragma unroll
            for (int pass = 0; pass < 3; pass++) {
                const uint32_t aB = sbase + Ao[pass];
                const uint32_t bB = sbase + PP_B + (uint32_t)j * 16384u + Bo[pass];
#pragma unroll
                for (int kc = 0; kc < 2; kc++) {
                    uint32_t a[2][4];
#pragma unroll
                    for (int mr = 0; mr < 2; mr++) {
                        int r = wr * 32 + mr * 16 + lq + (qq & 1) * 8;
                        int ci = kc * 2 + (qq >> 1);
                        ldsm_x4(a[mr], aB + sw_off(r, ci));
                    }
                    uint32_t bf[4][2];
#pragma unroll
                    for (int p = 0; p < 2; p++) {
                        int r = kc * 16 + lq + (qq & 1) * 8;
                        int ci = wc * 4 + p * 2 + (qq >> 1);
                        uint32_t t4r[4];
                        ldsm_x4_t(t4r, bB + sw_off(r, ci));
                        bf[2 * p][0] = t4r[0]; bf[2 * p][1] = t4r[1];
                        bf[2 * p + 1][0] = t4r[2]; bf[2 * p + 1][1] = t4r[3];
                    }
#pragma unroll
                    for (int mr = 0; mr < 2; mr++)
#pragma unroll
                        for (int nt = 0; nt < 4; nt++)
                            mma_bf16(acc[mr][nt], a[mr], bf[nt]);
                }
            }
#pragma unroll
            for (int mr = 0; mr < 2; mr++) {
#pragma unroll
                for (int half = 0; half < 2; half++) {
                    int i_row = wr * 32 + mr * 16 + half * 8 + grp;
                    int k = 2 * i_row + j;
#pragma unroll
                    for (int nt = 0; nt < 4; nt++) {
                        int c = wc * 32 + nt * 8 + tid4 * 2;
                        *(uint32_t*)(smb + PP_IMG + sw_off(k, c >> 3) + tid4 * 4) =
                            pack_h2(acc[mr][nt][half * 2 + 0], acc[mr][nt][half * 2 + 1]);
                    }
                }
            }
        }
        __syncthreads();

        // coalesced bulk store: 2048 float4 = 32KB
        float4* dst = (float4*)(g_Pimg + (size_t)(m * NN + n) * 16384);
        const float4* src = (const float4*)(smb + PP_IMG);
#pragma unroll
        for (int i = 0; i < 8; i++)
            dst[i * 256 + tid] = src[i * 256 + tid];
    }
}

// ---------------- fused kernel: 4 batches per block, 2 CTAs/SM, tensor attention ----------------
// smem bytes per CTA (106,496):
//  [A 0..24576)      96x128 fp16 swizzled (X during proj; Q image -> sO after)
//  [B 24576..57344)  P image during proj; W image (16KB) after
//  [K 57344..81920)  96x128 fp16 swizzled K image
//  [V 81920..106496) 96x128 fp16 swizzled V image
#define OFF_Bb 24576
#define OFF_K  57344
#define OFF_V  81920
#define SMEMF_TOTAL 106496

__global__ __launch_bounds__(256, 2) void fused_kernel(
    const float* __restrict__ query, const float* __restrict__ key_,
    const float* __restrict__ value,
    const float* __restrict__ outb,
    float* __restrict__ out, float* __restrict__ attn_out, int write_attn) {
    extern __shared__ float smf[];
    char* smb = (char*)smf;
    const uint32_t sbase = smem_u32(smb);

    const int n = blockIdx.x;
    const int b0 = blockIdx.y * G4;
    const int tid = threadIdx.x, wid = tid >> 5, lane = tid & 31;
    const int wr = wid >> 2, wc = wid & 3;        // warp grid 2(M) x 4(N)
    const int grp = lane >> 2, tid4 = lane & 3;
    const int lq = lane & 7, qq = lane >> 3;

    // ===== three projections (M=96 = 4 batches x 24), order k, v, q =====
    for (int mi = 0; mi < 3; mi++) {
        const int m = (mi + 1) % 3;               // 1, 2, 0
        if (mi) __syncthreads();
        {
            const char* bs = (const char*)(g_Pimg + (size_t)(m * NN + n) * 16384);
            uint32_t bd = sbase + OFF_Bb;
#pragma unroll
            for (int i = 0; i < 8; i++) {
                int c = i * 256 + tid;
                CP_ASYNC16(bd + c * 16, bs + c * 16);
            }
            CP_COMMIT();
        }
        {
            const float* x = (m == 0) ? query : ((m == 1) ? key_ : value);
#pragma unroll
            for (int it = 0; it < 12; it++) {
                int idx = it * 256 + tid;          // 3072 float4 jobs
                int r = idx >> 5, c4 = idx & 31;
                int g = r / TT, t = r - g * TT;
                float4 v = *(const float4*)(x + (((size_t)(b0 + g) * NN + n) * TT + t) * EE + 4 * c4);
                uint2 pk;
                pk.x = pack_h2(v.x, v.y);
                pk.y = pack_h2(v.z, v.w);
                uint32_t off = sw_off(r, c4 >> 1) + (uint32_t)(c4 & 1) * 8u;
                *(uint2*)(smb + off) = pk;
            }
        }
        CP_WAIT0();
        __syncthreads();

        // GEMM 96 x 128 x 128, single pass fp16
        float acc[3][4][4];
#pragma unroll
        for (int mr = 0; mr < 3; mr++)
#pragma unroll
            for (int nt = 0; nt < 4; nt++)
#pragma unroll
                for (int i = 0; i < 4; i++) acc[mr][nt][i] = 0.f;

#pragma unroll
        for (int kc = 0; kc < 8; kc++) {
            uint32_t a[3][4];
#pragma unroll
            for (int mr = 0; mr < 3; mr++) {
                int r = wr * 48 + mr * 16 + lq + (qq & 1) * 8;
                int ci = kc * 2 + (qq >> 1);
                ldsm_x4(a[mr], sbase + sw_off(r, ci));
            }
            uint32_t bf[4][2];
#pragma unroll
            for (int p = 0; p < 2; p++) {
                int r = kc * 16 + lq + (qq & 1) * 8;
                int ci = wc * 4 + p * 2 + (qq >> 1);
                uint32_t t4r[4];
                ldsm_x4_t(t4r, sbase + OFF_Bb + sw_off(r, ci));
                bf[2 * p][0] = t4r[0]; bf[2 * p][1] = t4r[1];
                bf[2 * p + 1][0] = t4r[2]; bf[2 * p + 1][1] = t4r[3];
            }
#pragma unroll
            for (int mr = 0; mr < 3; mr++)
#pragma unroll
                for (int nt = 0; nt < 4; nt++)
                    mma_f16(acc[mr][nt], a[mr], bf[nt]);
        }

        // epilogue: relu -> swizzled image (A for q, K/V images for k/v)
        const uint32_t obase = (m == 0) ? 0u : ((m == 1) ? (uint32_t)OFF_K : (uint32_t)OFF_V);
        if (m == 0) __syncthreads();   // all mma reads of A (X_query) done before overwrite
#pragma unroll
        for (int mr = 0; mr < 3; mr++) {
#pragma unroll
            for (int half = 0; half < 2; half++) {
                int row = wr * 48 + mr * 16 + half * 8 + grp;
#pragma unroll
                for (int nt = 0; nt < 4; nt++) {
                    int col = wc * 32 + nt * 8 + tid4 * 2;
                    *(uint32_t*)(smb + obase + sw_off(row, col >> 3) + (col & 7) * 2) =
                        pack_h2(fmaxf(acc[mr][nt][half * 2 + 0], 0.f),
                                fmaxf(acc[mr][nt][half * 2 + 1], 0.f));
                }
            }
        }
    }
    __syncthreads();      // Q image + K,V images complete

    // W image async copy into B region (overlaps attention)
    {
        const char* ws = (const char*)g_Wimg;
#pragma unroll
        for (int i = 0; i < 4; i++) {
            int c = i * 256 + tid;
            CP_ASYNC16(sbase + OFF_Bb + c * 16, ws + c * 16);
        }
        CP_COMMIT();
    }

    // ===== tensor-core attention: warp = head, loop over 4 batches, sync-free =====
    const int h = wid;                            // 8 warps = 8 heads
    const int ci_h = h * 2 + (qq >> 1);
#pragma unroll 1
    for (int g = 0; g < G4; g++) {
        const int rowb = g * TT;
        const long bn = (long)(b0 + g) * NN + n;

        // Q A-frags (2 m-tiles) and K B-frags (3 n-tiles of s)
        uint32_t aq[2][4], kf[2][4];
#pragma unroll
        for (int mt = 0; mt < 2; mt++) {
            int r = rowb + mt * 16 + lq + (qq & 1) * 8;
            if (r > 95) r = 95;
            ldsm_x4(aq[mt], sbase + sw_off(r, ci_h));
        }
#pragma unroll
        for (int st = 0; st < 2; st++) {
            int r = rowb + st * 16 + lq + (qq & 1) * 8;
            if (r > 95) r = 95;
            ldsm_x4(kf[st], sbase + OFF_K + sw_off(r, ci_h));
        }
        uint32_t bK[3][2];
        bK[0][0] = kf[0][0]; bK[0][1] = kf[0][2];
        bK[1][0] = kf[0][1]; bK[1][1] = kf[0][3];
        bK[2][0] = kf[1][0]; bK[2][1] = kf[1][2];

        float S[2][3][4];
#pragma unroll
        for (int mt = 0; mt < 2; mt++)
#pragma unroll
            for (int nt = 0; nt < 3; nt++) {
#pragma unroll
                for (int i = 0; i < 4; i++) S[mt][nt][i] = 0.f;
                mma_f16(S[mt][nt], aq[mt], bK[nt]);
            }

        // softmax over s (cols), causal mask, in fragments
#pragma unroll
        for (int mt = 0; mt < 2; mt++) {
#pragma unroll
            for (int rh = 0; rh < 2; rh++) {
                int tloc = mt * 16 + grp + rh * 8;
                float x[3][2];
                float mx = -1e30f;
#pragma unroll
                for (int nt = 0; nt < 3; nt++)
#pragma unroll
                    for (int c = 0; c < 2; c++) {
                        int s = nt * 8 + 2 * tid4 + c;
                        bool ok = (tloc < TT) && (s <= tloc);
                        float v = ok ? S[mt][nt][rh * 2 + c] * 0.25f : -1e30f;
                        x[nt][c] = v;
                        mx = fmaxf(mx, v);
                    }
                mx = fmaxf(mx, __shfl_xor_sync(0xffffffffu, mx, 1));
                mx = fmaxf(mx, __shfl_xor_sync(0xffffffffu, mx, 2));
                float sum = 0.f;
#pragma unroll
                for (int nt = 0; nt < 3; nt++)
#pragma unroll
                    for (int c = 0; c < 2; c++) {
                        float e = (x[nt][c] > -1e29f) ? __expf(x[nt][c] - mx) : 0.f;
                        x[nt][c] = e;
                        sum += e;
                    }
                sum += __shfl_xor_sync(0xffffffffu, sum, 1);
                sum += __shfl_xor_sync(0xffffffffu, sum, 2);
                float inv = (sum > 0.f) ? (1.f / sum) : 0.f;
#pragma unroll
                for (int nt = 0; nt < 3; nt++)
#pragma unroll
                    for (int c = 0; c < 2; c++)
                        S[mt][nt][rh * 2 + c] = x[nt][c] * inv;
            }
        }

        // write attn probabilities (fp32, valid rows only)
        if (write_attn) {
#pragma unroll
            for (int vr = 0; vr < 3; vr++) {      // (mt,rh) in {(0,0),(0,1),(1,0)}
                int mt = (vr == 2) ? 1 : 0;
                int rh = (vr == 1) ? 1 : 0;
                int tloc = mt * 16 + grp + rh * 8;
                float* ab = attn_out + (((bn * HH) + h) * TT + tloc) * TT + 2 * tid4;
#pragma unroll
                for (int nt = 0; nt < 3; nt++)
                    *(float2*)(ab + nt * 8) =
                        make_float2(S[mt][nt][rh * 2 + 0], S[mt][nt][rh * 2 + 1]);
            }
        }

        // pack P to fp16 A-frags: [mt][kchunk][4]
        uint32_t pa[2][2][4];
#pragma unroll
        for (int mt = 0; mt < 2; mt++) {
            pa[mt][0][0] = pack_h2(S[mt][0][0], S[mt][0][1]);
            pa[mt][0][1] = pack_h2(S[mt][0][2], S[mt][0][3]);
            pa[mt][0][2] = pack_h2(S[mt][1][0], S[mt][1][1]);
            pa[mt][0][3] = pack_h2(S[mt][1][2], S[mt][1][3]);
            pa[mt][1][0] = pack_h2(S[mt][2][0], S[mt][2][1]);
            pa[mt][1][1] = pack_h2(S[mt][2][2], S[mt][2][3]);
            pa[mt][1][2] = 0u;
            pa[mt][1][3] = 0u;
        }

        // V B-frags (2 k-chunks x 2 d-tiles)
        uint32_t vf[2][4];
#pragma unroll
        for (int kc = 0; kc < 2; kc++) {
            int r = rowb + kc * 16 + lq + (qq & 1) * 8;
            if (r > 95) r = 95;
            ldsm_x4_t(vf[kc], sbase + OFF_V + sw_off(r, ci_h));
        }

        float O[2][2][4];
#pragma unroll
        for (int mt = 0; mt < 2; mt++)
#pragma unroll
            for (int ntd = 0; ntd < 2; ntd++) {
#pragma unroll
                for (int i = 0; i < 4; i++) O[mt][ntd][i] = 0.f;
#pragma unroll
                for (int kc = 0; kc < 2; kc++) {
                    uint32_t bv[2] = {vf[kc][ntd * 2], vf[kc][ntd * 2 + 1]};
                    mma_f16(O[mt][ntd], pa[mt][kc], bv);
                }
            }

        // sO as fp16 into A image (same cols this warp read Q from)
#pragma unroll
        for (int mt = 0; mt < 2; mt++) {
#pragma unroll
            for (int ntd = 0; ntd < 2; ntd++) {
                int row0 = rowb + mt * 16 + grp;
                int col = h * 16 + ntd * 8 + 2 * tid4;
                *(uint32_t*)(smb + sw_off(row0, col >> 3) + (col & 7) * 2) =
                    pack_h2(O[mt][ntd][0], O[mt][ntd][1]);
                if (mt == 0)
                    *(uint32_t*)(smb + sw_off(row0 + 8, col >> 3) + (col & 7) * 2) =
                        pack_h2(O[mt][ntd][2], O[mt][ntd][3]);
            }
        }
    }
    CP_WAIT0();
    __syncthreads();      // sO image complete, W image ready

    // ===== output projection: (96x128) @ (128x64) mma, bias+relu =====
    {
        float acc[3][2][4];
#pragma unroll
        for (int mr = 0; mr < 3; mr++)
#pragma unroll
            for (int nt = 0; nt < 2; nt++)
#pragma unroll
                for (int i = 0; i < 4; i++) acc[mr][nt][i] = 0.f;

#pragma unroll
        for (int kc = 0; kc < 8; kc++) {
            uint32_t a[3][4];
#pragma unroll
            for (int mr = 0; mr < 3; mr++) {
                int r = wr * 48 + mr * 16 + lq + (qq & 1) * 8;
                int ci = kc * 2 + (qq >> 1);
                ldsm_x4(a[mr], sbase + sw_off(r, ci));
            }
            uint32_t bf[2][2];
            {
                int r = kc * 16 + lq + (qq & 1) * 8;
                int ci = wc * 2 + (qq >> 1);
                uint32_t t4r[4];
                ldsm_x4_t(t4r, sbase + OFF_Bb + sw_off64(r, ci));
                bf[0][0] = t4r[0]; bf[0][1] = t4r[1];
                bf[1][0] = t4r[2]; bf[1][1] = t4r[3];
            }
#pragma unroll
            for (int mr = 0; mr < 3; mr++)
#pragma unroll
                for (int nt = 0; nt < 2; nt++)
                    mma_f16(acc[mr][nt], a[mr], bf[nt]);
        }

        float2 bias[2];
#pragma unroll
        for (int nt = 0; nt < 2; nt++) {
            int col = wc * 16 + nt * 8 + tid4 * 2;
            bias[nt] = make_float2(__ldg(outb + col), __ldg(outb + col + 1));
        }
#pragma unroll
        for (int mr = 0; mr < 3; mr++) {
#pragma unroll
            for (int half = 0; half < 2; half++) {
                int row = wr * 48 + mr * 16 + half * 8 + grp;
                int g = row / TT, t2 = row - g * TT;
                const long bn = (long)(b0 + g) * NN + n;
                float* op = out + ((bn * TT) + t2) * DMOUT;
#pragma unroll
                for (int nt = 0; nt < 2; nt++) {
                    int col = wc * 16 + nt * 8 + tid4 * 2;
                    *(float2*)(op + col) = make_float2(
                        fmaxf(acc[mr][nt][half * 2 + 0] + bias[nt].x, 0.f),
                        fmaxf(acc[mr][nt][half * 2 + 1] + bias[nt].y, 0.f));
                }
            }
        }
    }
}

// ---------------- launch ----------------
extern "C" void kernel_launch(void* const* d_in, const int* in_sizes, int n_in,
                              void* d_out, int out_size) {
    const float* query = (const float*)d_in[0];
    const float* key_  = (const float*)d_in[1];
    const float* value = (const float*)d_in[2];
    const float* qp1 = (const float*)d_in[4];
    const float* qp2 = (const float*)d_in[5];
    const float* kp1 = (const float*)d_in[6];
    const float* kp2 = (const float*)d_in[7];
    const float* vp1 = (const float*)d_in[8];
    const float* vp2 = (const float*)d_in[9];
    const float* outW = (const float*)d_in[10];
    const float* outb = (const float*)d_in[11];

    float* out = (float*)d_out;
    int write_attn = (out_size >= OUT_N + ATTN_N) ? 1 : 0;

    static int attr_done = 0;
    if (!attr_done) {
        cudaFuncSetAttribute(prep_P_kernel, cudaFuncAttributeMaxDynamicSharedMemorySize, PP_SMEM);
        cudaFuncSetAttribute(fused_kernel, cudaFuncAttributeMaxDynamicSharedMemorySize, SMEMF_TOTAL);
        attr_done = 1;
    }

    prep_P_kernel<<<NN, 256, PP_SMEM>>>(qp1, qp2, kp1, kp2, vp1, vp2, outW);
    fused_kernel<<<dim3(NN, BB / G4), 256, SMEMF_TOTAL>>>(
        query, key_, value, outb, out, out + OUT_N, write_attn);
}